// round 6
// baseline (speedup 1.0000x reference)
#include <cuda_runtime.h>
#include <math.h>

// ---------------- problem constants ----------------
#define B_    2
#define T_    2048
#define TREF_ 512
#define C_    768
#define H_    12
#define D_    64
#define SK_   (T_ + TREF_)   // 2560

// ---------------- scratch (device globals; no cudaMalloc allowed) ----------
__device__ float g_q[(size_t)B_ * H_ * T_  * D_];   // (B,H,T,D)
__device__ float g_k[(size_t)B_ * H_ * SK_ * D_];   // (B,H,SK,D)  self keys [0,T), ref keys [T,SK)
__device__ float g_v[(size_t)B_ * H_ * SK_ * D_];
__device__ float g_y[(size_t)B_ * T_ * C_];         // attention output (B,T,H*D) before Wo

// ---------------------------------------------------------------------------
// Generic projection GEMM:  out = A(Mx768) @ W^T(768x768) + bias
//   A row-major [M][768], W row-major [768][768] (nn.Linear weight)
// Output scatter:
//   SKo == 0 : plain row-major out[m*768 + n]
//   SKo != 0 : head layout out[((b*H + h)*SKo + t + toff)*64 + d]
//              with b = m/Trows, t = m%Trows, h = n/64, d = n%64
// 64x64 tile, BK=16, 256 threads, 4x4 micro-tile, fp32.
// ---------------------------------------------------------------------------
__global__ __launch_bounds__(256)
void gemm_proj(const float* __restrict__ A, const float* __restrict__ W,
               const float* __restrict__ bias, float* __restrict__ out,
               int Trows, int SKo, int toff)
{
    __shared__ float As[16][64];   // k-major: As[k][m]
    __shared__ float Ws[16][64];   // k-major: Ws[k][n]

    const int tid = threadIdx.x;
    const int ty  = tid >> 4;      // 0..15 (row group)
    const int tx  = tid & 15;      // 0..15 (col group)
    const int m0  = blockIdx.y << 6;
    const int n0  = blockIdx.x << 6;
    const int lr  = tid >> 2;      // 0..63 load row
    const int lc  = tid & 3;       // 0..3  float4 group within 16-wide k slab

    const float* Ap = A + (size_t)(m0 + lr) * C_ + lc * 4;
    const float* Wp = W + (size_t)(n0 + lr) * C_ + lc * 4;

    float acc[4][4] = {};

    for (int k0 = 0; k0 < C_; k0 += 16) {
        float4 av = *(const float4*)(Ap + k0);
        float4 wv = *(const float4*)(Wp + k0);
        As[lc*4+0][lr] = av.x; As[lc*4+1][lr] = av.y;
        As[lc*4+2][lr] = av.z; As[lc*4+3][lr] = av.w;
        Ws[lc*4+0][lr] = wv.x; Ws[lc*4+1][lr] = wv.y;
        Ws[lc*4+2][lr] = wv.z; Ws[lc*4+3][lr] = wv.w;
        __syncthreads();

        #pragma unroll
        for (int kk = 0; kk < 16; kk++) {
            float4 a4 = *(const float4*)&As[kk][ty * 4];
            float4 b4 = *(const float4*)&Ws[kk][tx * 4];
            float a[4] = {a4.x, a4.y, a4.z, a4.w};
            float b[4] = {b4.x, b4.y, b4.z, b4.w};
            #pragma unroll
            for (int i = 0; i < 4; i++)
                #pragma unroll
                for (int j = 0; j < 4; j++)
                    acc[i][j] += a[i] * b[j];
        }
        __syncthreads();
    }

    float4 bvv = *(const float4*)(bias + n0 + tx * 4);
    const float bb[4] = {bvv.x, bvv.y, bvv.z, bvv.w};

    #pragma unroll
    for (int i = 0; i < 4; i++) {
        const int m = m0 + ty * 4 + i;
        float4 cv;
        cv.x = acc[i][0] + bb[0];
        cv.y = acc[i][1] + bb[1];
        cv.z = acc[i][2] + bb[2];
        cv.w = acc[i][3] + bb[3];
        if (SKo == 0) {
            *(float4*)(out + (size_t)m * C_ + n0 + tx * 4) = cv;
        } else {
            const int b = m / Trows, t = m % Trows;
            const int h = n0 >> 6;           // 64-wide N tile == one head
            const int d = tx * 4;
            const size_t idx = ((size_t)(b * H_ + h) * SKo + t + toff) * D_ + d;
            *(float4*)(out + idx) = cv;
        }
    }
}

// ---------------------------------------------------------------------------
// Fused flash attention with additive bias:
//   scores = Q·K^T * (1/8) + bias,  bias = (mask? -inf : rel_pos) on self keys,
//   0 on ref keys; online softmax; O = softmax(S)·V.
// One block = 64 query rows of one (b,h). 256 threads.
// Loops over 40 key blocks of 64 (SK=2560).
// ---------------------------------------------------------------------------
__global__ __launch_bounds__(256)
void attn_kernel(const int* __restrict__ mask, const float* __restrict__ rel,
                 float* __restrict__ yout)
{
    extern __shared__ float sm[];
    float (*Qs)[68] = (float(*)[68])(sm);              // Qs[r][d], pre-scaled
    float (*Kt)[68] = (float(*)[68])(sm + 64 * 68);    // Kt[d][c]  (transposed)
    float (*Vs)[68] = (float(*)[68])(sm + 2 * 64 * 68);// Vs[c][d]
    float (*Ss)[68] = (float(*)[68])(sm + 3 * 64 * 68);// Ss[r][c] scores -> probs
    float* m_s    = sm + 4 * 64 * 68;
    float* l_s    = m_s + 64;
    float* corr_s = l_s + 64;

    const float NI = __int_as_float(0xff800000);       // -inf

    const int tid = threadIdx.x;
    const int qb = blockIdx.x, h = blockIdx.y, b = blockIdx.z;
    const int tq0 = qb << 6;
    const int ty = tid >> 4, tx = tid & 15;            // compute mapping (16x16)
    const int lr = tid >> 2, lc = tid & 3;             // load mapping

    const float* Qg = g_q + ((size_t)(b * H_ + h) * T_  + tq0) * D_;
    const float* Kg = g_k +  (size_t)(b * H_ + h) * SK_ * D_;
    const float* Vg = g_v +  (size_t)(b * H_ + h) * SK_ * D_;

    // load Q tile, pre-scale by 1/sqrt(D) = 0.125
    #pragma unroll
    for (int ii = 0; ii < 4; ii++) {
        const int c4 = lc + ii * 4;
        float4 qv = *(const float4*)(Qg + lr * D_ + c4 * 4);
        qv.x *= 0.125f; qv.y *= 0.125f; qv.z *= 0.125f; qv.w *= 0.125f;
        *(float4*)&Qs[lr][c4 * 4] = qv;
    }
    if (tid < 64) { m_s[tid] = NI; l_s[tid] = 0.f; }
    float o[4][4] = {};
    __syncthreads();

    for (int kb = 0; kb < SK_ / 64; kb++) {
        const float* Kp = Kg + (size_t)kb * 64 * D_;
        const float* Vp = Vg + (size_t)kb * 64 * D_;
        // load K (transposed into Kt[d][c]) and V
        #pragma unroll
        for (int ii = 0; ii < 4; ii++) {
            const int c4 = lc + ii * 4;
            float4 kv = *(const float4*)(Kp + lr * D_ + c4 * 4);
            Kt[c4*4+0][lr] = kv.x; Kt[c4*4+1][lr] = kv.y;
            Kt[c4*4+2][lr] = kv.z; Kt[c4*4+3][lr] = kv.w;
            float4 vv = *(const float4*)(Vp + lr * D_ + c4 * 4);
            *(float4*)&Vs[lr][c4 * 4] = vv;
        }
        __syncthreads();

        // S = Qs @ Kt  (64x64x64)
        float acc[4][4] = {};
        #pragma unroll 16
        for (int d = 0; d < 64; d++) {
            const float a0 = Qs[ty*4+0][d];
            const float a1 = Qs[ty*4+1][d];
            const float a2 = Qs[ty*4+2][d];
            const float a3 = Qs[ty*4+3][d];
            const float4 b4 = *(const float4*)&Kt[d][tx * 4];
            acc[0][0] += a0*b4.x; acc[0][1] += a0*b4.y; acc[0][2] += a0*b4.z; acc[0][3] += a0*b4.w;
            acc[1][0] += a1*b4.x; acc[1][1] += a1*b4.y; acc[1][2] += a1*b4.z; acc[1][3] += a1*b4.w;
            acc[2][0] += a2*b4.x; acc[2][1] += a2*b4.y; acc[2][2] += a2*b4.z; acc[2][3] += a2*b4.w;
            acc[3][0] += a3*b4.x; acc[3][1] += a3*b4.y; acc[3][2] += a3*b4.z; acc[3][3] += a3*b4.w;
        }

        // apply bias + write S to smem
        const int tk0 = kb * 64 + tx * 4;
        if (kb < T_ / 64) {            // self keys: mask + rel_pos
            #pragma unroll
            for (int i = 0; i < 4; i++) {
                const int tq = tq0 + ty * 4 + i;
                const int4   mv = *(const int4*)  (mask + (size_t)(b * T_ + tq) * T_ + tk0);
                const float4 rv = *(const float4*)(rel + ((size_t)h * T_ + tq) * T_ + tk0);
                Ss[ty*4+i][tx*4+0] = (mv.x == 1) ? NI : acc[i][0] + rv.x;
                Ss[ty*4+i][tx*4+1] = (mv.y == 1) ? NI : acc[i][1] + rv.y;
                Ss[ty*4+i][tx*4+2] = (mv.z == 1) ? NI : acc[i][2] + rv.z;
                Ss[ty*4+i][tx*4+3] = (mv.w == 1) ? NI : acc[i][3] + rv.w;
            }
        } else {                       // ref keys: bias = 0
            #pragma unroll
            for (int i = 0; i < 4; i++) {
                Ss[ty*4+i][tx*4+0] = acc[i][0];
                Ss[ty*4+i][tx*4+1] = acc[i][1];
                Ss[ty*4+i][tx*4+2] = acc[i][2];
                Ss[ty*4+i][tx*4+3] = acc[i][3];
            }
        }
        __syncthreads();

        // online softmax: 4 lanes per row
        {
            const int row = tid >> 2, q = tid & 3;
            float mloc = NI;
            #pragma unroll
            for (int j = 0; j < 16; j++) mloc = fmaxf(mloc, Ss[row][q * 16 + j]);
            mloc = fmaxf(mloc, __shfl_xor_sync(0xffffffffu, mloc, 1));
            mloc = fmaxf(mloc, __shfl_xor_sync(0xffffffffu, mloc, 2));
            const float mold = m_s[row];
            const float mnew = fmaxf(mold, mloc);
            float corr = (mold == NI) ? 0.f : __expf(mold - mnew);
            float lloc = 0.f;
            #pragma unroll
            for (int j = 0; j < 16; j++) {
                const float s = Ss[row][q * 16 + j];
                const float p = (s == NI) ? 0.f : __expf(s - mnew);
                Ss[row][q * 16 + j] = p;
                lloc += p;
            }
            lloc += __shfl_xor_sync(0xffffffffu, lloc, 1);
            lloc += __shfl_xor_sync(0xffffffffu, lloc, 2);
            if (q == 0) {
                m_s[row]    = mnew;
                corr_s[row] = corr;
                l_s[row]    = l_s[row] * corr + lloc;
            }
        }
        __syncthreads();

        // O = O*corr + P @ V
        {
            const float c0 = corr_s[ty*4+0];
            const float c1 = corr_s[ty*4+1];
            const float c2 = corr_s[ty*4+2];
            const float c3 = corr_s[ty*4+3];
            #pragma unroll
            for (int j = 0; j < 4; j++) {
                o[0][j] *= c0; o[1][j] *= c1; o[2][j] *= c2; o[3][j] *= c3;
            }
            #pragma unroll 16
            for (int c = 0; c < 64; c++) {
                const float p0 = Ss[ty*4+0][c];
                const float p1 = Ss[ty*4+1][c];
                const float p2 = Ss[ty*4+2][c];
                const float p3 = Ss[ty*4+3][c];
                const float4 v4 = *(const float4*)&Vs[c][tx * 4];
                o[0][0] += p0*v4.x; o[0][1] += p0*v4.y; o[0][2] += p0*v4.z; o[0][3] += p0*v4.w;
                o[1][0] += p1*v4.x; o[1][1] += p1*v4.y; o[1][2] += p1*v4.z; o[1][3] += p1*v4.w;
                o[2][0] += p2*v4.x; o[2][1] += p2*v4.y; o[2][2] += p2*v4.z; o[2][3] += p2*v4.w;
                o[3][0] += p3*v4.x; o[3][1] += p3*v4.y; o[3][2] += p3*v4.z; o[3][3] += p3*v4.w;
            }
        }
        __syncthreads();
    }

    // finalize: divide by l, write (B,T,H*D)
    #pragma unroll
    for (int i = 0; i < 4; i++) {
        const int tq = tq0 + ty * 4 + i;
        const float inv = 1.0f / l_s[ty * 4 + i];
        float4 w;
        w.x = o[i][0] * inv; w.y = o[i][1] * inv;
        w.z = o[i][2] * inv; w.w = o[i][3] * inv;
        *(float4*)(yout + (size_t)(b * T_ + tq) * C_ + h * D_ + tx * 4) = w;
    }
}

// ---------------------------------------------------------------------------
extern "C" void kernel_launch(void* const* d_in, const int* in_sizes, int n_in,
                              void* d_out, int out_size)
{
    const float* x    = (const float*)d_in[0];
    const int*   mask = (const int*)  d_in[1];
    const float* rel  = (const float*)d_in[2];
    const float* ref  = (const float*)d_in[3];
    const float* Wq   = (const float*)d_in[4];  const float* bq  = (const float*)d_in[5];
    const float* Wk   = (const float*)d_in[6];  const float* bk  = (const float*)d_in[7];
    const float* Wv   = (const float*)d_in[8];  const float* bv  = (const float*)d_in[9];
    const float* Wrk  = (const float*)d_in[10]; const float* brk = (const float*)d_in[11];
    const float* Wrv  = (const float*)d_in[12]; const float* brv = (const float*)d_in[13];
    const float* Wo   = (const float*)d_in[14]; const float* bo  = (const float*)d_in[15];
    float* out = (float*)d_out;

    float *qp, *kp, *vp, *yp;
    cudaGetSymbolAddress((void**)&qp, g_q);
    cudaGetSymbolAddress((void**)&kp, g_k);
    cudaGetSymbolAddress((void**)&vp, g_v);
    cudaGetSymbolAddress((void**)&yp, g_y);

    const dim3 blk(256);
    const dim3 gMain(C_ / 64, (B_ * T_)    / 64);   // 12 x 64
    const dim3 gRef (C_ / 64, (B_ * TREF_) / 64);   // 12 x 16

    // projections
    gemm_proj<<<gMain, blk>>>(x,   Wq,  bq,  qp, T_,    T_,  0);    // Q  -> (B,H,T,D)
    gemm_proj<<<gMain, blk>>>(x,   Wk,  bk,  kp, T_,    SK_, 0);    // K  -> (B,H,SK,D)[0,T)
    gemm_proj<<<gMain, blk>>>(x,   Wv,  bv,  vp, T_,    SK_, 0);    // V
    gemm_proj<<<gRef,  blk>>>(ref, Wrk, brk, kp, TREF_, SK_, T_);   // RK -> [T,SK)
    gemm_proj<<<gRef,  blk>>>(ref, Wrv, brv, vp, TREF_, SK_, T_);   // RV

    // fused attention
    const size_t smem = (4 * 64 * 68 + 3 * 64) * sizeof(float);     // 70400 B
    cudaFuncSetAttribute(attn_kernel, cudaFuncAttributeMaxDynamicSharedMemorySize, (int)smem);
    attn_kernel<<<dim3(T_ / 64, H_, B_), blk, smem>>>(mask, rel, yp);

    // output projection
    gemm_proj<<<gMain, blk>>>(yp, Wo, bo, out, T_, 0, 0);
}

// round 7
// speedup vs baseline: 1.0545x; 1.0545x over previous
#include <cuda_runtime.h>
#include <math.h>

// ---------------- problem constants ----------------
#define B_    2
#define T_    2048
#define TREF_ 512
#define C_    768
#define H_    12
#define D_    64
#define SK_   (T_ + TREF_)   // 2560

// ---------------- scratch (device globals; no cudaMalloc allowed) ----------
__device__ float g_q[(size_t)B_ * H_ * T_  * D_];   // (B,H,T,D)
__device__ float g_k[(size_t)B_ * H_ * SK_ * D_];   // (B,H,SK,D)  self keys [0,T), ref keys [T,SK)
__device__ float g_v[(size_t)B_ * H_ * SK_ * D_];
__device__ float g_y[(size_t)B_ * T_ * C_];         // attention output (B,T,H*D) before Wo

// ---------------------------------------------------------------------------
// Generic projection GEMM:  out = A(Mx768) @ W^T(768x768) + bias
//   A row-major [M][768], W row-major [768][768] (nn.Linear weight)
// Output scatter:
//   SKo == 0 : plain row-major out[m*768 + n]
//   SKo != 0 : head layout out[((b*H + h)*SKo + t + toff)*64 + d]
//              with b = m/Trows, t = m%Trows, h = n/64, d = n%64
// 64x64 tile, BK=16, 256 threads, 4x4 micro-tile, fp32.
// ---------------------------------------------------------------------------
__global__ __launch_bounds__(256)
void gemm_proj(const float* __restrict__ A, const float* __restrict__ W,
               const float* __restrict__ bias, float* __restrict__ out,
               int Trows, int SKo, int toff)
{
    __shared__ float As[16][64];   // k-major: As[k][m]
    __shared__ float Ws[16][64];   // k-major: Ws[k][n]

    const int tid = threadIdx.x;
    const int ty  = tid >> 4;      // 0..15 (row group)
    const int tx  = tid & 15;      // 0..15 (col group)
    const int m0  = blockIdx.y << 6;
    const int n0  = blockIdx.x << 6;
    const int lr  = tid >> 2;      // 0..63 load row
    const int lc  = tid & 3;       // 0..3  float4 group within 16-wide k slab

    const float* Ap = A + (size_t)(m0 + lr) * C_ + lc * 4;
    const float* Wp = W + (size_t)(n0 + lr) * C_ + lc * 4;

    float acc[4][4] = {};

    for (int k0 = 0; k0 < C_; k0 += 16) {
        float4 av = *(const float4*)(Ap + k0);
        float4 wv = *(const float4*)(Wp + k0);
        As[lc*4+0][lr] = av.x; As[lc*4+1][lr] = av.y;
        As[lc*4+2][lr] = av.z; As[lc*4+3][lr] = av.w;
        Ws[lc*4+0][lr] = wv.x; Ws[lc*4+1][lr] = wv.y;
        Ws[lc*4+2][lr] = wv.z; Ws[lc*4+3][lr] = wv.w;
        __syncthreads();

        #pragma unroll
        for (int kk = 0; kk < 16; kk++) {
            float4 a4 = *(const float4*)&As[kk][ty * 4];
            float4 b4 = *(const float4*)&Ws[kk][tx * 4];
            float a[4] = {a4.x, a4.y, a4.z, a4.w};
            float b[4] = {b4.x, b4.y, b4.z, b4.w};
            #pragma unroll
            for (int i = 0; i < 4; i++)
                #pragma unroll
                for (int j = 0; j < 4; j++)
                    acc[i][j] += a[i] * b[j];
        }
        __syncthreads();
    }

    float4 bvv = *(const float4*)(bias + n0 + tx * 4);
    const float bb[4] = {bvv.x, bvv.y, bvv.z, bvv.w};

    #pragma unroll
    for (int i = 0; i < 4; i++) {
        const int m = m0 + ty * 4 + i;
        float4 cv;
        cv.x = acc[i][0] + bb[0];
        cv.y = acc[i][1] + bb[1];
        cv.z = acc[i][2] + bb[2];
        cv.w = acc[i][3] + bb[3];
        if (SKo == 0) {
            *(float4*)(out + (size_t)m * C_ + n0 + tx * 4) = cv;
        } else {
            const int b = m / Trows, t = m % Trows;
            const int h = n0 >> 6;           // 64-wide N tile == one head
            const int d = tx * 4;
            const size_t idx = ((size_t)(b * H_ + h) * SKo + t + toff) * D_ + d;
            *(float4*)(out + idx) = cv;
        }
    }
}

// ---------------------------------------------------------------------------
// Fused flash attention with additive bias:
//   scores = Q·K^T * (1/8) + bias,  bias = (mask? -inf : rel_pos) on self keys,
//   0 on ref keys; online softmax; O = softmax(S)·V.
// One block = 64 query rows of one (b,h). 256 threads.
// Loops over 40 key blocks of 64 (SK=2560).
// ---------------------------------------------------------------------------
__global__ __launch_bounds__(256)
void attn_kernel(const int* __restrict__ mask, const float* __restrict__ rel,
                 float* __restrict__ yout)
{
    extern __shared__ float sm[];
    float (*Qs)[68] = (float(*)[68])(sm);              // Qs[r][d], pre-scaled
    float (*Kt)[68] = (float(*)[68])(sm + 64 * 68);    // Kt[d][c]  (transposed)
    float (*Vs)[68] = (float(*)[68])(sm + 2 * 64 * 68);// Vs[c][d]
    float (*Ss)[68] = (float(*)[68])(sm + 3 * 64 * 68);// Ss[r][c] scores -> probs
    float* m_s    = sm + 4 * 64 * 68;
    float* l_s    = m_s + 64;
    float* corr_s = l_s + 64;

    const float NI = __int_as_float(0xff800000);       // -inf

    const int tid = threadIdx.x;
    const int qb = blockIdx.x, h = blockIdx.y, b = blockIdx.z;
    const int tq0 = qb << 6;
    const int ty = tid >> 4, tx = tid & 15;            // compute mapping (16x16)
    const int lr = tid >> 2, lc = tid & 3;             // load mapping

    const float* Qg = g_q + ((size_t)(b * H_ + h) * T_  + tq0) * D_;
    const float* Kg = g_k +  (size_t)(b * H_ + h) * SK_ * D_;
    const float* Vg = g_v +  (size_t)(b * H_ + h) * SK_ * D_;

    // load Q tile, pre-scale by 1/sqrt(D) = 0.125
    #pragma unroll
    for (int ii = 0; ii < 4; ii++) {
        const int c4 = lc + ii * 4;
        float4 qv = *(const float4*)(Qg + lr * D_ + c4 * 4);
        qv.x *= 0.125f; qv.y *= 0.125f; qv.z *= 0.125f; qv.w *= 0.125f;
        *(float4*)&Qs[lr][c4 * 4] = qv;
    }
    if (tid < 64) { m_s[tid] = NI; l_s[tid] = 0.f; }
    float o[4][4] = {};
    __syncthreads();

    for (int kb = 0; kb < SK_ / 64; kb++) {
        const float* Kp = Kg + (size_t)kb * 64 * D_;
        const float* Vp = Vg + (size_t)kb * 64 * D_;
        // load K (transposed into Kt[d][c]) and V
        #pragma unroll
        for (int ii = 0; ii < 4; ii++) {
            const int c4 = lc + ii * 4;
            float4 kv = *(const float4*)(Kp + lr * D_ + c4 * 4);
            Kt[c4*4+0][lr] = kv.x; Kt[c4*4+1][lr] = kv.y;
            Kt[c4*4+2][lr] = kv.z; Kt[c4*4+3][lr] = kv.w;
            float4 vv = *(const float4*)(Vp + lr * D_ + c4 * 4);
            *(float4*)&Vs[lr][c4 * 4] = vv;
        }
        __syncthreads();

        // S = Qs @ Kt  (64x64x64)
        float acc[4][4] = {};
        #pragma unroll 16
        for (int d = 0; d < 64; d++) {
            const float a0 = Qs[ty*4+0][d];
            const float a1 = Qs[ty*4+1][d];
            const float a2 = Qs[ty*4+2][d];
            const float a3 = Qs[ty*4+3][d];
            const float4 b4 = *(const float4*)&Kt[d][tx * 4];
            acc[0][0] += a0*b4.x; acc[0][1] += a0*b4.y; acc[0][2] += a0*b4.z; acc[0][3] += a0*b4.w;
            acc[1][0] += a1*b4.x; acc[1][1] += a1*b4.y; acc[1][2] += a1*b4.z; acc[1][3] += a1*b4.w;
            acc[2][0] += a2*b4.x; acc[2][1] += a2*b4.y; acc[2][2] += a2*b4.z; acc[2][3] += a2*b4.w;
            acc[3][0] += a3*b4.x; acc[3][1] += a3*b4.y; acc[3][2] += a3*b4.z; acc[3][3] += a3*b4.w;
        }

        // apply bias + write S to smem
        const int tk0 = kb * 64 + tx * 4;
        if (kb < T_ / 64) {            // self keys: mask + rel_pos
            #pragma unroll
            for (int i = 0; i < 4; i++) {
                const int tq = tq0 + ty * 4 + i;
                const int4   mv = *(const int4*)  (mask + (size_t)(b * T_ + tq) * T_ + tk0);
                const float4 rv = *(const float4*)(rel + ((size_t)h * T_ + tq) * T_ + tk0);
                Ss[ty*4+i][tx*4+0] = (mv.x == 1) ? NI : acc[i][0] + rv.x;
                Ss[ty*4+i][tx*4+1] = (mv.y == 1) ? NI : acc[i][1] + rv.y;
                Ss[ty*4+i][tx*4+2] = (mv.z == 1) ? NI : acc[i][2] + rv.z;
                Ss[ty*4+i][tx*4+3] = (mv.w == 1) ? NI : acc[i][3] + rv.w;
            }
        } else {                       // ref keys: bias = 0
            #pragma unroll
            for (int i = 0; i < 4; i++) {
                Ss[ty*4+i][tx*4+0] = acc[i][0];
                Ss[ty*4+i][tx*4+1] = acc[i][1];
                Ss[ty*4+i][tx*4+2] = acc[i][2];
                Ss[ty*4+i][tx*4+3] = acc[i][3];
            }
        }
        __syncthreads();

        // online softmax: 4 lanes per row
        {
            const int row = tid >> 2, q = tid & 3;
            float mloc = NI;
            #pragma unroll
            for (int j = 0; j < 16; j++) mloc = fmaxf(mloc, Ss[row][q * 16 + j]);
            mloc = fmaxf(mloc, __shfl_xor_sync(0xffffffffu, mloc, 1));
            mloc = fmaxf(mloc, __shfl_xor_sync(0xffffffffu, mloc, 2));
            const float mold = m_s[row];
            const float mnew = fmaxf(mold, mloc);
            float corr = (mold == NI) ? 0.f : __expf(mold - mnew);
            float lloc = 0.f;
            #pragma unroll
            for (int j = 0; j < 16; j++) {
                const float s = Ss[row][q * 16 + j];
                const float p = (s == NI) ? 0.f : __expf(s - mnew);
                Ss[row][q * 16 + j] = p;
                lloc += p;
            }
            lloc += __shfl_xor_sync(0xffffffffu, lloc, 1);
            lloc += __shfl_xor_sync(0xffffffffu, lloc, 2);
            if (q == 0) {
                m_s[row]    = mnew;
                corr_s[row] = corr;
                l_s[row]    = l_s[row] * corr + lloc;
            }
        }
        __syncthreads();

        // O = O*corr + P @ V
        {
            const float c0 = corr_s[ty*4+0];
            const float c1 = corr_s[ty*4+1];
            const float c2 = corr_s[ty*4+2];
            const float c3 = corr_s[ty*4+3];
            #pragma unroll
            for (int j = 0; j < 4; j++) {
                o[0][j] *= c0; o[1][j] *= c1; o[2][j] *= c2; o[3][j] *= c3;
            }
            #pragma unroll 16
            for (int c = 0; c < 64; c++) {
                const float p0 = Ss[ty*4+0][c];
                const float p1 = Ss[ty*4+1][c];
                const float p2 = Ss[ty*4+2][c];
                const float p3 = Ss[ty*4+3][c];
                const float4 v4 = *(const float4*)&Vs[c][tx * 4];
                o[0][0] += p0*v4.x; o[0][1] += p0*v4.y; o[0][2] += p0*v4.z; o[0][3] += p0*v4.w;
                o[1][0] += p1*v4.x; o[1][1] += p1*v4.y; o[1][2] += p1*v4.z; o[1][3] += p1*v4.w;
                o[2][0] += p2*v4.x; o[2][1] += p2*v4.y; o[2][2] += p2*v4.z; o[2][3] += p2*v4.w;
                o[3][0] += p3*v4.x; o[3][1] += p3*v4.y; o[3][2] += p3*v4.z; o[3][3] += p3*v4.w;
            }
        }
        __syncthreads();
    }

    // finalize: divide by l, write (B,T,H*D)
    #pragma unroll
    for (int i = 0; i < 4; i++) {
        const int tq = tq0 + ty * 4 + i;
        const float inv = 1.0f / l_s[ty * 4 + i];
        float4 w;
        w.x = o[i][0] * inv; w.y = o[i][1] * inv;
        w.z = o[i][2] * inv; w.w = o[i][3] * inv;
        *(float4*)(yout + (size_t)(b * T_ + tq) * C_ + h * D_ + tx * 4) = w;
    }
}

// ---------------------------------------------------------------------------
extern "C" void kernel_launch(void* const* d_in, const int* in_sizes, int n_in,
                              void* d_out, int out_size)
{
    const float* x    = (const float*)d_in[0];
    const int*   mask = (const int*)  d_in[1];
    const float* rel  = (const float*)d_in[2];
    const float* ref  = (const float*)d_in[3];
    const float* Wq   = (const float*)d_in[4];  const float* bq  = (const float*)d_in[5];
    const float* Wk   = (const float*)d_in[6];  const float* bk  = (const float*)d_in[7];
    const float* Wv   = (const float*)d_in[8];  const float* bv  = (const float*)d_in[9];
    const float* Wrk  = (const float*)d_in[10]; const float* brk = (const float*)d_in[11];
    const float* Wrv  = (const float*)d_in[12]; const float* brv = (const float*)d_in[13];
    const float* Wo   = (const float*)d_in[14]; const float* bo  = (const float*)d_in[15];
    float* out = (float*)d_out;

    float *qp, *kp, *vp, *yp;
    cudaGetSymbolAddress((void**)&qp, g_q);
    cudaGetSymbolAddress((void**)&kp, g_k);
    cudaGetSymbolAddress((void**)&vp, g_v);
    cudaGetSymbolAddress((void**)&yp, g_y);

    const dim3 blk(256);
    const dim3 gMain(C_ / 64, (B_ * T_)    / 64);   // 12 x 64
    const dim3 gRef (C_ / 64, (B_ * TREF_) / 64);   // 12 x 16

    // projections
    gemm_proj<<<gMain, blk>>>(x,   Wq,  bq,  qp, T_,    T_,  0);    // Q  -> (B,H,T,D)
    gemm_proj<<<gMain, blk>>>(x,   Wk,  bk,  kp, T_,    SK_, 0);    // K  -> (B,H,SK,D)[0,T)
    gemm_proj<<<gMain, blk>>>(x,   Wv,  bv,  vp, T_,    SK_, 0);    // V
    gemm_proj<<<gRef,  blk>>>(ref, Wrk, brk, kp, TREF_, SK_, T_);   // RK -> [T,SK)
    gemm_proj<<<gRef,  blk>>>(ref, Wrv, brv, vp, TREF_, SK_, T_);   // RV

    // fused attention
    const size_t smem = (4 * 64 * 68 + 3 * 64) * sizeof(float);     // 70400 B
    cudaFuncSetAttribute(attn_kernel, cudaFuncAttributeMaxDynamicSharedMemorySize, (int)smem);
    attn_kernel<<<dim3(T_ / 64, H_, B_), blk, smem>>>(mask, rel, yp);

    // output projection
    gemm_proj<<<gMain, blk>>>(yp, Wo, bo, out, T_, 0, 0);
}

// round 10
// speedup vs baseline: 1.5542x; 1.4739x over previous
#include <cuda_runtime.h>
#include <cuda_bf16.h>
#include <cstdint>
#include <math.h>

#define B_    2
#define T_    2048
#define TREF_ 512
#define C_    768
#define H_    12
#define D_    64
#define SK_   (T_ + TREF_)

__device__ float g_q[(size_t)B_ * H_ * T_  * D_];
__device__ float g_k[(size_t)B_ * H_ * SK_ * D_];
__device__ float g_v[(size_t)B_ * H_ * SK_ * D_];
__device__ float g_y[(size_t)B_ * T_ * C_];
__device__ __nv_bfloat16 g_xh[(size_t)B_ * T_ * C_],    g_xl[(size_t)B_ * T_ * C_];
__device__ __nv_bfloat16 g_rh[(size_t)B_ * TREF_ * C_], g_rl[(size_t)B_ * TREF_ * C_];
__device__ __nv_bfloat16 g_wh[6 * C_ * C_],             g_wl[6 * C_ * C_];
__device__ __nv_bfloat16 g_yh[(size_t)B_ * T_ * C_],    g_yl[(size_t)B_ * T_ * C_];

// ---------------- helpers ----------------
__device__ __forceinline__ uint32_t smem_u32(const void* p) {
    uint32_t a;
    asm("{ .reg .u64 t; cvta.to.shared.u64 t, %1; cvt.u32.u64 %0, t; }" : "=r"(a) : "l"(p));
    return a;
}
#define SW128(o) ((o) ^ (((o) >> 3) & 0x70))

__device__ __forceinline__ void ldmx4(uint32_t* r, uint32_t addr) {
    asm volatile("ldmatrix.sync.aligned.m8n8.x4.shared.b16 {%0,%1,%2,%3}, [%4];"
                 : "=r"(r[0]), "=r"(r[1]), "=r"(r[2]), "=r"(r[3]) : "r"(addr));
}
__device__ __forceinline__ void mma_bf16(float* d, const uint32_t* a, const uint32_t* b) {
    asm volatile("mma.sync.aligned.m16n8k16.row.col.f32.bf16.bf16.f32 "
                 "{%0,%1,%2,%3}, {%4,%5,%6,%7}, {%8,%9}, {%0,%1,%2,%3};"
                 : "+f"(d[0]), "+f"(d[1]), "+f"(d[2]), "+f"(d[3])
                 : "r"(a[0]), "r"(a[1]), "r"(a[2]), "r"(a[3]), "r"(b[0]), "r"(b[1]));
}
__device__ __forceinline__ void cp16(uint32_t saddr, const void* g) {
    asm volatile("cp.async.cg.shared.global [%0], [%1], 16;" :: "r"(saddr), "l"(g));
}
#define CP_COMMIT() asm volatile("cp.async.commit_group;" ::: "memory")

// ---------------- fp32 -> bf16 hi/lo split ----------------
__global__ __launch_bounds__(256)
void split_kernel(const float* __restrict__ src, __nv_bfloat16* __restrict__ hi,
                  __nv_bfloat16* __restrict__ lo, int n4)
{
    const int i = blockIdx.x * 256 + threadIdx.x;
    if (i >= n4) return;
    const float4 a = ((const float4*)src)[i];
    float av[4] = {a.x, a.y, a.z, a.w};
    __nv_bfloat16 hv[4], lv[4];
    #pragma unroll
    for (int j = 0; j < 4; j++) {
        hv[j] = __float2bfloat16(av[j]);
        lv[j] = __float2bfloat16(av[j] - __bfloat162float(hv[j]));
    }
    ((__nv_bfloat162*)hi)[2*i+0] = __nv_bfloat162(hv[0], hv[1]);
    ((__nv_bfloat162*)hi)[2*i+1] = __nv_bfloat162(hv[2], hv[3]);
    ((__nv_bfloat162*)lo)[2*i+0] = __nv_bfloat162(lv[0], lv[1]);
    ((__nv_bfloat162*)lo)[2*i+1] = __nv_bfloat162(lv[2], lv[3]);
}

// ---------------- split-bf16 mma.sync GEMM ----------------
// out(128x64 per block) = A(Mx768) @ W^T + bias, K in 12 chunks of 64.
// Stage (48KB): Ah[128][64] 16K | Al 16K | Bh[64][64] 8K | Bl 8K (SW128, 128B rows)
#define STSZ  49152
#define GSMEM (2 * STSZ)

__device__ __forceinline__ void cp_stage(uint32_t sbase,
    const __nv_bfloat16* __restrict__ Ah, const __nv_bfloat16* __restrict__ Al,
    const __nv_bfloat16* __restrict__ Bh, const __nv_bfloat16* __restrict__ Bl,
    int m0, int n0, int k0, int tid)
{
    #pragma unroll
    for (int i = 0; i < 4; i++) {                 // A: 128 rows x 8 chunks of 16B
        const int u = tid + 256 * i, r = u >> 3, g = u & 7;
        const size_t go = (size_t)(m0 + r) * C_ + k0 + g * 8;
        const uint32_t so = SW128((uint32_t)(r * 128 + g * 16));
        cp16(sbase + so,         Ah + go);
        cp16(sbase + 16384 + so, Al + go);
    }
    #pragma unroll
    for (int i = 0; i < 2; i++) {                 // B: 64 rows x 8 chunks
        const int u = tid + 256 * i, r = u >> 3, g = u & 7;
        const size_t go = (size_t)(n0 + r) * C_ + k0 + g * 8;
        const uint32_t so = SW128((uint32_t)(r * 128 + g * 16));
        cp16(sbase + 32768 + so, Bh + go);
        cp16(sbase + 40960 + so, Bl + go);
    }
}

__global__ __launch_bounds__(256)
void gemm_mma(const __nv_bfloat16* __restrict__ Ah, const __nv_bfloat16* __restrict__ Al,
              const __nv_bfloat16* __restrict__ Bh, const __nv_bfloat16* __restrict__ Bl,
              const float* __restrict__ bias, float* __restrict__ out,
              int Trows, int SKo, int toff)
{
    extern __shared__ char smem[];
    const uint32_t sb = smem_u32(smem);
    const int tid = threadIdx.x, lane = tid & 31, wid = tid >> 5;
    const int wm = wid & 3, wn = wid >> 2;          // 4 m-groups x 2 n-groups
    const int n0 = blockIdx.x * 64, m0 = blockIdx.y * 128;

    float D[2][4][4] = {};

    cp_stage(sb, Ah, Al, Bh, Bl, m0, n0, 0, tid);
    CP_COMMIT();

    // per-lane ldmatrix row/byte offsets (within a 128B-row SW128 tile)
    const int arow0 = wm * 32 + (lane & 15);
    const uint32_t akb = ((uint32_t)(lane >> 4)) << 4;
    const int brow0 = wn * 32 + ((lane >> 4) << 3) + (lane & 7);
    const uint32_t bkb = ((uint32_t)((lane >> 3) & 1)) << 4;

    #pragma unroll 1
    for (int c = 0; c < 12; c++) {
        if (c + 1 < 12) {
            cp_stage(sb + ((c + 1) & 1) * STSZ, Ah, Al, Bh, Bl, m0, n0, (c + 1) * 64, tid);
            CP_COMMIT();
            asm volatile("cp.async.wait_group 1;" ::: "memory");
        } else {
            asm volatile("cp.async.wait_group 0;" ::: "memory");
        }
        __syncthreads();

        const uint32_t bA = sb + (c & 1) * STSZ;
        const uint32_t bB = bA + 32768;

        #pragma unroll
        for (int ks = 0; ks < 4; ks++) {
            uint32_t ah[2][4], al[2][4], bh[2][4], bl[2][4];
            #pragma unroll
            for (int ms = 0; ms < 2; ms++) {
                const uint32_t off = SW128((uint32_t)((arow0 + ms * 16) * 128) + ks * 32 + akb);
                ldmx4(ah[ms], bA + off);
                ldmx4(al[ms], bA + 16384 + off);
            }
            #pragma unroll
            for (int nj = 0; nj < 2; nj++) {
                const uint32_t off = SW128((uint32_t)((brow0 + nj * 16) * 128) + ks * 32 + bkb);
                ldmx4(bh[nj], bB + off);
                ldmx4(bl[nj], bB + 8192 + off);
            }
            #pragma unroll
            for (int ms = 0; ms < 2; ms++)
                #pragma unroll
                for (int ns = 0; ns < 4; ns++) {
                    const uint32_t* fh = &bh[ns >> 1][(ns & 1) * 2];
                    const uint32_t* fl = &bl[ns >> 1][(ns & 1) * 2];
                    mma_bf16(D[ms][ns], ah[ms], fh);   // Ah*Bh
                    mma_bf16(D[ms][ns], ah[ms], fl);   // Ah*Bl
                    mma_bf16(D[ms][ns], al[ms], fh);   // Al*Bh
                }
        }
        __syncthreads();
    }

    // epilogue: fragment -> global (+bias, head scatter)
    const int h = n0 >> 6;
    #pragma unroll
    for (int ns = 0; ns < 4; ns++) {
        const int col = n0 + wn * 32 + ns * 8 + (lane & 3) * 2;
        const float b0 = bias[col], b1 = bias[col + 1];
        #pragma unroll
        for (int ms = 0; ms < 2; ms++) {
            const int r0 = m0 + wm * 32 + ms * 16 + (lane >> 2);
            #pragma unroll
            for (int half = 0; half < 2; half++) {
                const int m = r0 + half * 8;
                const float v0 = D[ms][ns][half * 2 + 0] + b0;
                const float v1 = D[ms][ns][half * 2 + 1] + b1;
                if (SKo == 0) {
                    *(float2*)(out + (size_t)m * C_ + col) = make_float2(v0, v1);
                } else {
                    const int bi = m / Trows, t = m % Trows, d = col - n0;
                    *(float2*)(out + ((size_t)(bi * H_ + h) * SKo + t + toff) * D_ + d) =
                        make_float2(v0, v1);
                }
            }
        }
    }
}

// ---------------- fused flash attention (known-correct, unchanged) ----------
__global__ __launch_bounds__(256)
void attn_kernel(const int* __restrict__ mask, const float* __restrict__ rel,
                 float* __restrict__ yout)
{
    extern __shared__ float sm[];
    float (*Qs)[68] = (float(*)[68])(sm);
    float (*Kt)[68] = (float(*)[68])(sm + 64 * 68);
    float (*Vs)[68] = (float(*)[68])(sm + 2 * 64 * 68);
    float (*Ss)[68] = (float(*)[68])(sm + 3 * 64 * 68);
    float* m_s = sm + 4 * 64 * 68;
    float* l_s = m_s + 64;
    float* corr_s = l_s + 64;
    const float NI = __int_as_float(0xff800000);

    const int tid = threadIdx.x;
    const int qb = blockIdx.x, h = blockIdx.y, b = blockIdx.z;
    const int tq0 = qb << 6;
    const int ty = tid >> 4, tx = tid & 15;
    const int lr = tid >> 2, lc = tid & 3;

    const float* Qg = g_q + ((size_t)(b * H_ + h) * T_  + tq0) * D_;
    const float* Kg = g_k +  (size_t)(b * H_ + h) * SK_ * D_;
    const float* Vg = g_v +  (size_t)(b * H_ + h) * SK_ * D_;

    #pragma unroll
    for (int ii = 0; ii < 4; ii++) {
        const int c4 = lc + ii * 4;
        float4 qv = *(const float4*)(Qg + lr * D_ + c4 * 4);
        qv.x *= 0.125f; qv.y *= 0.125f; qv.z *= 0.125f; qv.w *= 0.125f;
        *(float4*)&Qs[lr][c4 * 4] = qv;
    }
    if (tid < 64) { m_s[tid] = NI; l_s[tid] = 0.f; }
    float o[4][4] = {};
    __syncthreads();

    for (int kb = 0; kb < SK_ / 64; kb++) {
        const float* Kp = Kg + (size_t)kb * 64 * D_;
        const float* Vp = Vg + (size_t)kb * 64 * D_;
        #pragma unroll
        for (int ii = 0; ii < 4; ii++) {
            const int c4 = lc + ii * 4;
            float4 kv = *(const float4*)(Kp + lr * D_ + c4 * 4);
            Kt[c4*4+0][lr] = kv.x; Kt[c4*4+1][lr] = kv.y;
            Kt[c4*4+2][lr] = kv.z; Kt[c4*4+3][lr] = kv.w;
            float4 vv = *(const float4*)(Vp + lr * D_ + c4 * 4);
            *(float4*)&Vs[lr][c4 * 4] = vv;
        }
        __syncthreads();

        float acc[4][4] = {};
        #pragma unroll 16
        for (int d = 0; d < 64; d++) {
            const float a0 = Qs[ty*4+0][d], a1 = Qs[ty*4+1][d];
            const float a2 = Qs[ty*4+2][d], a3 = Qs[ty*4+3][d];
            const float4 b4 = *(const float4*)&Kt[d][tx * 4];
            acc[0][0]+=a0*b4.x; acc[0][1]+=a0*b4.y; acc[0][2]+=a0*b4.z; acc[0][3]+=a0*b4.w;
            acc[1][0]+=a1*b4.x; acc[1][1]+=a1*b4.y; acc[1][2]+=a1*b4.z; acc[1][3]+=a1*b4.w;
            acc[2][0]+=a2*b4.x; acc[2][1]+=a2*b4.y; acc[2][2]+=a2*b4.z; acc[2][3]+=a2*b4.w;
            acc[3][0]+=a3*b4.x; acc[3][1]+=a3*b4.y; acc[3][2]+=a3*b4.z; acc[3][3]+=a3*b4.w;
        }

        const int tk0 = kb * 64 + tx * 4;
        if (kb < T_ / 64) {
            #pragma unroll
            for (int i = 0; i < 4; i++) {
                const int tq = tq0 + ty * 4 + i;
                const int4   mv = *(const int4*)  (mask + (size_t)(b * T_ + tq) * T_ + tk0);
                const float4 rv = *(const float4*)(rel + ((size_t)h * T_ + tq) * T_ + tk0);
                Ss[ty*4+i][tx*4+0] = (mv.x == 1) ? NI : acc[i][0] + rv.x;
                Ss[ty*4+i][tx*4+1] = (mv.y == 1) ? NI : acc[i][1] + rv.y;
                Ss[ty*4+i][tx*4+2] = (mv.z == 1) ? NI : acc[i][2] + rv.z;
                Ss[ty*4+i][tx*4+3] = (mv.w == 1) ? NI : acc[i][3] + rv.w;
            }
        } else {
            #pragma unroll
            for (int i = 0; i < 4; i++) {
                Ss[ty*4+i][tx*4+0] = acc[i][0]; Ss[ty*4+i][tx*4+1] = acc[i][1];
                Ss[ty*4+i][tx*4+2] = acc[i][2]; Ss[ty*4+i][tx*4+3] = acc[i][3];
            }
        }
        __syncthreads();

        {
            const int row = tid >> 2, q = tid & 3;
            float mloc = NI;
            #pragma unroll
            for (int j = 0; j < 16; j++) mloc = fmaxf(mloc, Ss[row][q * 16 + j]);
            mloc = fmaxf(mloc, __shfl_xor_sync(0xffffffffu, mloc, 1));
            mloc = fmaxf(mloc, __shfl_xor_sync(0xffffffffu, mloc, 2));
            const float mold = m_s[row];
            const float mnew = fmaxf(mold, mloc);
            float corr = (mold == NI) ? 0.f : __expf(mold - mnew);
            float lloc = 0.f;
            #pragma unroll
            for (int j = 0; j < 16; j++) {
                const float s = Ss[row][q * 16 + j];
                const float p = (s == NI) ? 0.f : __expf(s - mnew);
                Ss[row][q * 16 + j] = p;
                lloc += p;
            }
            lloc += __shfl_xor_sync(0xffffffffu, lloc, 1);
            lloc += __shfl_xor_sync(0xffffffffu, lloc, 2);
            if (q == 0) {
                m_s[row] = mnew; corr_s[row] = corr;
                l_s[row] = l_s[row] * corr + lloc;
            }
        }
        __syncthreads();

        {
            const float c0 = corr_s[ty*4+0], c1 = corr_s[ty*4+1];
            const float c2 = corr_s[ty*4+2], c3 = corr_s[ty*4+3];
            #pragma unroll
            for (int j = 0; j < 4; j++) {
                o[0][j] *= c0; o[1][j] *= c1; o[2][j] *= c2; o[3][j] *= c3;
            }
            #pragma unroll 16
            for (int c = 0; c < 64; c++) {
                const float p0 = Ss[ty*4+0][c], p1 = Ss[ty*4+1][c];
                const float p2 = Ss[ty*4+2][c], p3 = Ss[ty*4+3][c];
                const float4 v4 = *(const float4*)&Vs[c][tx * 4];
                o[0][0]+=p0*v4.x; o[0][1]+=p0*v4.y; o[0][2]+=p0*v4.z; o[0][3]+=p0*v4.w;
                o[1][0]+=p1*v4.x; o[1][1]+=p1*v4.y; o[1][2]+=p1*v4.z; o[1][3]+=p1*v4.w;
                o[2][0]+=p2*v4.x; o[2][1]+=p2*v4.y; o[2][2]+=p2*v4.z; o[2][3]+=p2*v4.w;
                o[3][0]+=p3*v4.x; o[3][1]+=p3*v4.y; o[3][2]+=p3*v4.z; o[3][3]+=p3*v4.w;
            }
        }
        __syncthreads();
    }

    #pragma unroll
    for (int i = 0; i < 4; i++) {
        const int tq = tq0 + ty * 4 + i;
        const float inv = 1.0f / l_s[ty * 4 + i];
        float4 w;
        w.x = o[i][0]*inv; w.y = o[i][1]*inv; w.z = o[i][2]*inv; w.w = o[i][3]*inv;
        *(float4*)(yout + (size_t)(b * T_ + tq) * C_ + h * D_ + tx * 4) = w;
    }
}

// ---------------------------------------------------------------------------
extern "C" void kernel_launch(void* const* d_in, const int* in_sizes, int n_in,
                              void* d_out, int out_size)
{
    const float* x    = (const float*)d_in[0];
    const int*   mask = (const int*)  d_in[1];
    const float* rel  = (const float*)d_in[2];
    const float* ref  = (const float*)d_in[3];
    const float* W[6] = {(const float*)d_in[4], (const float*)d_in[6], (const float*)d_in[8],
                         (const float*)d_in[10], (const float*)d_in[12], (const float*)d_in[14]};
    const float* bias[6] = {(const float*)d_in[5], (const float*)d_in[7], (const float*)d_in[9],
                            (const float*)d_in[11], (const float*)d_in[13], (const float*)d_in[15]};
    float* out = (float*)d_out;

    float *qp, *kp, *vp, *yp;
    cudaGetSymbolAddress((void**)&qp, g_q);
    cudaGetSymbolAddress((void**)&kp, g_k);
    cudaGetSymbolAddress((void**)&vp, g_v);
    cudaGetSymbolAddress((void**)&yp, g_y);
    __nv_bfloat16 *xh, *xl, *rh, *rl, *wh, *wl, *yh, *yl;
    cudaGetSymbolAddress((void**)&xh, g_xh); cudaGetSymbolAddress((void**)&xl, g_xl);
    cudaGetSymbolAddress((void**)&rh, g_rh); cudaGetSymbolAddress((void**)&rl, g_rl);
    cudaGetSymbolAddress((void**)&wh, g_wh); cudaGetSymbolAddress((void**)&wl, g_wl);
    cudaGetSymbolAddress((void**)&yh, g_yh); cudaGetSymbolAddress((void**)&yl, g_yl);

    cudaFuncSetAttribute(gemm_mma, cudaFuncAttributeMaxDynamicSharedMemorySize, GSMEM);
    cudaFuncSetAttribute(attn_kernel, cudaFuncAttributeMaxDynamicSharedMemorySize,
                         (int)((4 * 64 * 68 + 3 * 64) * sizeof(float)));

    const dim3 blk(256);
    const int NX4 = B_ * T_ * C_ / 4, NR4 = B_ * TREF_ * C_ / 4, NW4 = C_ * C_ / 4;

    split_kernel<<<(NX4 + 255) / 256, blk>>>(x,   xh, xl, NX4);
    split_kernel<<<(NR4 + 255) / 256, blk>>>(ref, rh, rl, NR4);
    for (int i = 0; i < 6; i++)
        split_kernel<<<(NW4 + 255) / 256, blk>>>(W[i], wh + (size_t)i * C_ * C_,
                                                 wl + (size_t)i * C_ * C_, NW4);

    const dim3 gMain(C_ / 64, (B_ * T_)    / 128);  // 12 x 32
    const dim3 gRef (C_ / 64, (B_ * TREF_) / 128);  // 12 x 8
    const size_t WSZ = (size_t)C_ * C_;

    gemm_mma<<<gMain, blk, GSMEM>>>(xh, xl, wh + 0*WSZ, wl + 0*WSZ, bias[0], qp, T_,    T_,  0);
    gemm_mma<<<gMain, blk, GSMEM>>>(xh, xl, wh + 1*WSZ, wl + 1*WSZ, bias[1], kp, T_,    SK_, 0);
    gemm_mma<<<gMain, blk, GSMEM>>>(xh, xl, wh + 2*WSZ, wl + 2*WSZ, bias[2], vp, T_,    SK_, 0);
    gemm_mma<<<gRef,  blk, GSMEM>>>(rh, rl, wh + 3*WSZ, wl + 3*WSZ, bias[3], kp, TREF_, SK_, T_);
    gemm_mma<<<gRef,  blk, GSMEM>>>(rh, rl, wh + 4*WSZ, wl + 4*WSZ, bias[4], vp, TREF_, SK_, T_);

    const size_t asm_sz = (4 * 64 * 68 + 3 * 64) * sizeof(float);
    attn_kernel<<<dim3(T_ / 64, H_, B_), blk, asm_sz>>>(mask, rel, yp);

    split_kernel<<<(NX4 + 255) / 256, blk>>>(yp, yh, yl, NX4);
    gemm_mma<<<gMain, blk, GSMEM>>>(yh, yl, wh + 5*WSZ, wl + 5*WSZ, bias[5], out, T_, 0, 0);
}

// round 11
// speedup vs baseline: 2.3188x; 1.4920x over previous
#include <cuda_runtime.h>
#include <cuda_bf16.h>
#include <cstdint>
#include <math.h>

#define B_    2
#define T_    2048
#define TREF_ 512
#define C_    768
#define H_    12
#define D_    64
#define SK_   (T_ + TREF_)

__device__ float g_q[(size_t)B_ * H_ * T_  * D_];
__device__ float g_k[(size_t)B_ * H_ * SK_ * D_];
__device__ float g_v[(size_t)B_ * H_ * SK_ * D_];
__device__ float g_y[(size_t)B_ * T_ * C_];
__device__ __nv_bfloat16 g_xh[(size_t)B_ * T_ * C_],    g_xl[(size_t)B_ * T_ * C_];
__device__ __nv_bfloat16 g_rh[(size_t)B_ * TREF_ * C_], g_rl[(size_t)B_ * TREF_ * C_];
__device__ __nv_bfloat16 g_wh[6 * C_ * C_],             g_wl[6 * C_ * C_];
__device__ __nv_bfloat16 g_yh[(size_t)B_ * T_ * C_],    g_yl[(size_t)B_ * T_ * C_];
// attention operands (bf16 hi/lo)
__device__ __nv_bfloat16 g_qh[(size_t)B_ * H_ * T_  * D_], g_ql[(size_t)B_ * H_ * T_ * D_];
__device__ __nv_bfloat16 g_kh[(size_t)B_ * H_ * SK_ * D_], g_kl[(size_t)B_ * H_ * SK_ * D_];
__device__ __nv_bfloat16 g_vth[(size_t)B_ * H_ * D_ * SK_], g_vtl[(size_t)B_ * H_ * D_ * SK_];

// ---------------- helpers ----------------
__device__ __forceinline__ uint32_t smem_u32(const void* p) {
    uint32_t a;
    asm("{ .reg .u64 t; cvta.to.shared.u64 t, %1; cvt.u32.u64 %0, t; }" : "=r"(a) : "l"(p));
    return a;
}
#define SW128(o) ((o) ^ (((o) >> 3) & 0x70))

__device__ __forceinline__ void ldmx4(uint32_t* r, uint32_t addr) {
    asm volatile("ldmatrix.sync.aligned.m8n8.x4.shared.b16 {%0,%1,%2,%3}, [%4];"
                 : "=r"(r[0]), "=r"(r[1]), "=r"(r[2]), "=r"(r[3]) : "r"(addr));
}
__device__ __forceinline__ void mma_bf16(float* d, const uint32_t* a, const uint32_t* b) {
    asm volatile("mma.sync.aligned.m16n8k16.row.col.f32.bf16.bf16.f32 "
                 "{%0,%1,%2,%3}, {%4,%5,%6,%7}, {%8,%9}, {%0,%1,%2,%3};"
                 : "+f"(d[0]), "+f"(d[1]), "+f"(d[2]), "+f"(d[3])
                 : "r"(a[0]), "r"(a[1]), "r"(a[2]), "r"(a[3]), "r"(b[0]), "r"(b[1]));
}
__device__ __forceinline__ void cp16(uint32_t saddr, const void* g) {
    asm volatile("cp.async.cg.shared.global [%0], [%1], 16;" :: "r"(saddr), "l"(g));
}
#define CP_COMMIT() asm volatile("cp.async.commit_group;" ::: "memory")
#define CP_WAIT(n)  asm volatile("cp.async.wait_group %0;" :: "n"(n) : "memory")

// 3-term split-bf16 MMA over one 32(A-rows)x32(B-rows)x64 tile (4 ksteps).
// A tiles at baseAh/baseAl (row-major, SW128 128B rows), B same.
__device__ __forceinline__ void mma_block3(float Dv[2][4][4],
    uint32_t baseAh, uint32_t baseAl, uint32_t baseBh, uint32_t baseBl,
    int arow0, uint32_t akb, int brow0, uint32_t bkb)
{
    #pragma unroll
    for (int ks = 0; ks < 4; ks++) {
        uint32_t ah[2][4], al[2][4], bh[2][4], bl[2][4];
        #pragma unroll
        for (int ms = 0; ms < 2; ms++) {
            const uint32_t off = SW128((uint32_t)((arow0 + ms * 16) * 128) + ks * 32 + akb);
            ldmx4(ah[ms], baseAh + off);
            ldmx4(al[ms], baseAl + off);
        }
        #pragma unroll
        for (int nj = 0; nj < 2; nj++) {
            const uint32_t off = SW128((uint32_t)((brow0 + nj * 16) * 128) + ks * 32 + bkb);
            ldmx4(bh[nj], baseBh + off);
            ldmx4(bl[nj], baseBl + off);
        }
        #pragma unroll
        for (int ms = 0; ms < 2; ms++)
            #pragma unroll
            for (int ns = 0; ns < 4; ns++) {
                const uint32_t* fh = &bh[ns >> 1][(ns & 1) * 2];
                const uint32_t* fl = &bl[ns >> 1][(ns & 1) * 2];
                mma_bf16(Dv[ms][ns], ah[ms], fh);
                mma_bf16(Dv[ms][ns], ah[ms], fl);
                mma_bf16(Dv[ms][ns], al[ms], fh);
            }
    }
}

// ---------------- fp32 -> bf16 hi/lo split (optionally scaled) -------------
__global__ __launch_bounds__(256)
void split_kernel(const float* __restrict__ src, __nv_bfloat16* __restrict__ hi,
                  __nv_bfloat16* __restrict__ lo, int n4, float scale)
{
    const int i = blockIdx.x * 256 + threadIdx.x;
    if (i >= n4) return;
    const float4 a = ((const float4*)src)[i];
    float av[4] = {a.x * scale, a.y * scale, a.z * scale, a.w * scale};
    __nv_bfloat16 hv[4], lv[4];
    #pragma unroll
    for (int j = 0; j < 4; j++) {
        hv[j] = __float2bfloat16(av[j]);
        lv[j] = __float2bfloat16(av[j] - __bfloat162float(hv[j]));
    }
    ((__nv_bfloat162*)hi)[2*i+0] = __nv_bfloat162(hv[0], hv[1]);
    ((__nv_bfloat162*)hi)[2*i+1] = __nv_bfloat162(hv[2], hv[3]);
    ((__nv_bfloat162*)lo)[2*i+0] = __nv_bfloat162(lv[0], lv[1]);
    ((__nv_bfloat162*)lo)[2*i+1] = __nv_bfloat162(lv[2], lv[3]);
}

// ---------------- V transpose + split: v[(bh),t,d] -> vt[(bh),d,t] --------
__global__ __launch_bounds__(256)
void vt_split(const float* __restrict__ v, __nv_bfloat16* __restrict__ vth,
              __nv_bfloat16* __restrict__ vtl)
{
    __shared__ float S[64][68];
    const int bh = blockIdx.y, t0 = blockIdx.x * 64, tid = threadIdx.x;
    const float* src = v + ((size_t)bh * SK_ + t0) * D_;
    #pragma unroll
    for (int it = 0; it < 4; it++) {
        const int u = tid + 256 * it, r = u >> 4, c4 = u & 15;
        const float4 x = *(const float4*)(src + (size_t)r * D_ + c4 * 4);
        *(float4*)&S[r][c4 * 4] = x;
    }
    __syncthreads();
    #pragma unroll
    for (int it = 0; it < 2; it++) {
        const int u = tid + 256 * it, d = u >> 3, ch = u & 7;
        uint32_t wh[4], wl[4];
        #pragma unroll
        for (int p = 0; p < 4; p++) {
            const float f0 = S[ch * 8 + p * 2 + 0][d];
            const float f1 = S[ch * 8 + p * 2 + 1][d];
            __nv_bfloat16 h0 = __float2bfloat16(f0), h1 = __float2bfloat16(f1);
            __nv_bfloat162 hp(h0, h1);
            __nv_bfloat162 lp(__float2bfloat16(f0 - __bfloat162float(h0)),
                              __float2bfloat16(f1 - __bfloat162float(h1)));
            wh[p] = *(uint32_t*)&hp; wl[p] = *(uint32_t*)&lp;
        }
        const size_t o = ((size_t)bh * D_ + d) * SK_ + t0 + ch * 8;
        *(uint4*)(vth + o) = make_uint4(wh[0], wh[1], wh[2], wh[3]);
        *(uint4*)(vtl + o) = make_uint4(wl[0], wl[1], wl[2], wl[3]);
    }
}

// ---------------- split-bf16 mma.sync GEMM (unchanged from R10) ------------
#define STSZ  49152
#define GSMEM (2 * STSZ)

__device__ __forceinline__ void cp_stage(uint32_t sbase,
    const __nv_bfloat16* __restrict__ Ah, const __nv_bfloat16* __restrict__ Al,
    const __nv_bfloat16* __restrict__ Bh, const __nv_bfloat16* __restrict__ Bl,
    int m0, int n0, int k0, int tid)
{
    #pragma unroll
    for (int i = 0; i < 4; i++) {
        const int u = tid + 256 * i, r = u >> 3, g = u & 7;
        const size_t go = (size_t)(m0 + r) * C_ + k0 + g * 8;
        const uint32_t so = SW128((uint32_t)(r * 128 + g * 16));
        cp16(sbase + so,         Ah + go);
        cp16(sbase + 16384 + so, Al + go);
    }
    #pragma unroll
    for (int i = 0; i < 2; i++) {
        const int u = tid + 256 * i, r = u >> 3, g = u & 7;
        const size_t go = (size_t)(n0 + r) * C_ + k0 + g * 8;
        const uint32_t so = SW128((uint32_t)(r * 128 + g * 16));
        cp16(sbase + 32768 + so, Bh + go);
        cp16(sbase + 40960 + so, Bl + go);
    }
}

__global__ __launch_bounds__(256)
void gemm_mma(const __nv_bfloat16* __restrict__ Ah, const __nv_bfloat16* __restrict__ Al,
              const __nv_bfloat16* __restrict__ Bh, const __nv_bfloat16* __restrict__ Bl,
              const float* __restrict__ bias, float* __restrict__ out,
              int Trows, int SKo, int toff)
{
    extern __shared__ char smem[];
    const uint32_t sb = smem_u32(smem);
    const int tid = threadIdx.x, lane = tid & 31, wid = tid >> 5;
    const int wm = wid & 3, wn = wid >> 2;
    const int n0 = blockIdx.x * 64, m0 = blockIdx.y * 128;

    float D[2][4][4] = {};
    cp_stage(sb, Ah, Al, Bh, Bl, m0, n0, 0, tid);
    CP_COMMIT();

    const int arow0 = wm * 32 + (lane & 15);
    const uint32_t akb = ((uint32_t)(lane >> 4)) << 4;
    const int brow0 = wn * 32 + ((lane >> 4) << 3) + (lane & 7);
    const uint32_t bkb = ((uint32_t)((lane >> 3) & 1)) << 4;

    #pragma unroll 1
    for (int c = 0; c < 12; c++) {
        if (c + 1 < 12) {
            cp_stage(sb + ((c + 1) & 1) * STSZ, Ah, Al, Bh, Bl, m0, n0, (c + 1) * 64, tid);
            CP_COMMIT();
            CP_WAIT(1);
        } else CP_WAIT(0);
        __syncthreads();
        const uint32_t bA = sb + (c & 1) * STSZ;
        mma_block3(D, bA, bA + 16384, bA + 32768, bA + 40960, arow0, akb, brow0, bkb);
        __syncthreads();
    }

    const int h = n0 >> 6;
    #pragma unroll
    for (int ns = 0; ns < 4; ns++) {
        const int col = n0 + wn * 32 + ns * 8 + (lane & 3) * 2;
        const float b0 = bias[col], b1 = bias[col + 1];
        #pragma unroll
        for (int ms = 0; ms < 2; ms++) {
            const int r0 = m0 + wm * 32 + ms * 16 + (lane >> 2);
            #pragma unroll
            for (int half = 0; half < 2; half++) {
                const int m = r0 + half * 8;
                const float v0 = D[ms][ns][half * 2 + 0] + b0;
                const float v1 = D[ms][ns][half * 2 + 1] + b1;
                if (SKo == 0) {
                    *(float2*)(out + (size_t)m * C_ + col) = make_float2(v0, v1);
                } else {
                    const int bi = m / Trows, t = m % Trows, d = col - n0;
                    *(float2*)(out + ((size_t)(bi * H_ + h) * SKo + t + toff) * D_ + d) =
                        make_float2(v0, v1);
                }
            }
        }
    }
}

// ---------------- mma.sync flash attention (split-bf16, 128 q-rows/block) --
#define AS_QH  0
#define AS_QL  16384
#define AS_STG 32768              /* +s*32768: KH 0 | KL 8192 | VTH 16384 | VTL 24576 */
#define AS_SS  98304              /* fp32 128x68 */
#define AS_PH  133120
#define AS_PL  149504
#define AS_ST  165888             /* m_s,l_s,corr_s : 128 f each */
#define ASMEM  167424

__global__ __launch_bounds__(256)
void attn_mma(const int* __restrict__ mask, const float* __restrict__ rel,
              const __nv_bfloat16* __restrict__ qh, const __nv_bfloat16* __restrict__ ql,
              const __nv_bfloat16* __restrict__ kh, const __nv_bfloat16* __restrict__ kl,
              const __nv_bfloat16* __restrict__ vth, const __nv_bfloat16* __restrict__ vtl,
              float* __restrict__ yout)
{
    extern __shared__ char smem[];
    const uint32_t sb = smem_u32(smem);
    float* Ss     = (float*)(smem + AS_SS);          // pitch 68
    float* m_s    = (float*)(smem + AS_ST);
    float* l_s    = m_s + 128;
    float* corr_s = m_s + 256;
    const float NI = __int_as_float(0xff800000);

    const int tid = threadIdx.x, lane = tid & 31, wid = tid >> 5;
    const int wm = wid & 3, wn = wid >> 2;
    const int qb = blockIdx.x, h = blockIdx.y, b = blockIdx.z;
    const int tq0 = qb * 128, bh = b * H_ + h;

    const int arow0 = wm * 32 + (lane & 15);
    const uint32_t akb = ((uint32_t)(lane >> 4)) << 4;
    const int brow0 = wn * 32 + ((lane >> 4) << 3) + (lane & 7);
    const uint32_t bkb = ((uint32_t)((lane >> 3) & 1)) << 4;

    // Q tiles (persist) + stage 0, one commit group
    {
        const size_t qbase = ((size_t)bh * T_ + tq0) * D_;
        #pragma unroll
        for (int it = 0; it < 4; it++) {
            const int u = tid + 256 * it, r = u >> 3, g = u & 7;
            const uint32_t so = SW128((uint32_t)(r * 128 + g * 16));
            cp16(sb + AS_QH + so, qh + qbase + (size_t)r * D_ + g * 8);
            cp16(sb + AS_QL + so, ql + qbase + (size_t)r * D_ + g * 8);
        }
        const size_t kbase = (size_t)bh * SK_ * D_;
        const size_t vbase = (size_t)bh * D_ * SK_;
        #pragma unroll
        for (int it = 0; it < 2; it++) {
            const int u = tid + 256 * it, r = u >> 3, g = u & 7;
            const uint32_t so = SW128((uint32_t)(r * 128 + g * 16));
            cp16(sb + AS_STG + so,         kh + kbase + (size_t)r * D_ + g * 8);
            cp16(sb + AS_STG + 8192 + so,  kl + kbase + (size_t)r * D_ + g * 8);
            cp16(sb + AS_STG + 16384 + so, vth + vbase + (size_t)r * SK_ + g * 8);
            cp16(sb + AS_STG + 24576 + so, vtl + vbase + (size_t)r * SK_ + g * 8);
        }
        CP_COMMIT();
    }
    if (tid < 128) { m_s[tid] = NI; l_s[tid] = 0.f; }
    float O[2][4][4] = {};

    #pragma unroll 1
    for (int kb = 0; kb < SK_ / 64; kb++) {
        if (kb + 1 < SK_ / 64) {
            const uint32_t st = sb + AS_STG + ((kb + 1) & 1) * 32768;
            const size_t kbase = ((size_t)bh * SK_ + (kb + 1) * 64) * D_;
            const size_t vbase = (size_t)bh * D_ * SK_ + (kb + 1) * 64;
            #pragma unroll
            for (int it = 0; it < 2; it++) {
                const int u = tid + 256 * it, r = u >> 3, g = u & 7;
                const uint32_t so = SW128((uint32_t)(r * 128 + g * 16));
                cp16(st + so,         kh + kbase + (size_t)r * D_ + g * 8);
                cp16(st + 8192 + so,  kl + kbase + (size_t)r * D_ + g * 8);
                cp16(st + 16384 + so, vth + vbase + (size_t)r * SK_ + g * 8);
                cp16(st + 24576 + so, vtl + vbase + (size_t)r * SK_ + g * 8);
            }
            CP_COMMIT();
            CP_WAIT(1);
        } else CP_WAIT(0);
        __syncthreads();

        const uint32_t stg = sb + AS_STG + (kb & 1) * 32768;

        // --- QK: S = Q*K^T (pre-scaled Q) ---
        float Dq[2][4][4] = {};
        mma_block3(Dq, sb + AS_QH, sb + AS_QL, stg, stg + 8192, arow0, akb, brow0, bkb);

        // frags -> smem S (fp32)
        #pragma unroll
        for (int ms = 0; ms < 2; ms++)
            #pragma unroll
            for (int ns = 0; ns < 4; ns++) {
                const int col = wn * 32 + ns * 8 + (lane & 3) * 2;
                #pragma unroll
                for (int half = 0; half < 2; half++) {
                    const int r = wm * 32 + ms * 16 + (lane >> 2) + half * 8;
                    *(float2*)&Ss[r * 68 + col] =
                        make_float2(Dq[ms][ns][half * 2], Dq[ms][ns][half * 2 + 1]);
                }
            }
        __syncthreads();

        // --- bias + online softmax: 2 threads per row, 32 cols each ---
        {
            const int row = tid >> 1, ch = (tid & 1) * 32;
            float sv[32];
            if (kb < T_ / 64) {
                const int tq = tq0 + row;
                const int*   mp = mask + ((size_t)b * T_ + tq) * T_ + kb * 64 + ch;
                const float* rp = rel  + ((size_t)h * T_ + tq) * T_ + kb * 64 + ch;
                #pragma unroll
                for (int j = 0; j < 8; j++) {
                    const int4   mv = *(const int4*)(mp + j * 4);
                    const float4 rv = *(const float4*)(rp + j * 4);
                    const float4 s  = *(const float4*)&Ss[row * 68 + ch + j * 4];
                    sv[j*4+0] = (mv.x == 1) ? NI : s.x + rv.x;
                    sv[j*4+1] = (mv.y == 1) ? NI : s.y + rv.y;
                    sv[j*4+2] = (mv.z == 1) ? NI : s.z + rv.z;
                    sv[j*4+3] = (mv.w == 1) ? NI : s.w + rv.w;
                }
            } else {
                #pragma unroll
                for (int j = 0; j < 8; j++) {
                    const float4 s = *(const float4*)&Ss[row * 68 + ch + j * 4];
                    sv[j*4+0] = s.x; sv[j*4+1] = s.y; sv[j*4+2] = s.z; sv[j*4+3] = s.w;
                }
            }
            float mloc = NI;
            #pragma unroll
            for (int j = 0; j < 32; j++) mloc = fmaxf(mloc, sv[j]);
            mloc = fmaxf(mloc, __shfl_xor_sync(0xffffffffu, mloc, 1));
            const float mold = m_s[row];
            const float mnew = fmaxf(mold, mloc);
            const float corr = (mold == NI) ? 0.f : __expf(mold - mnew);
            float lloc = 0.f;
            #pragma unroll
            for (int j = 0; j < 32; j++) {
                const float p = (sv[j] == NI) ? 0.f : __expf(sv[j] - mnew);
                sv[j] = p; lloc += p;
            }
            // write P hi/lo (bf16, SW128 rows)
            #pragma unroll
            for (int cc = 0; cc < 4; cc++) {
                uint32_t wh[4], wl[4];
                #pragma unroll
                for (int p2 = 0; p2 < 4; p2++) {
                    const float f0 = sv[cc * 8 + p2 * 2 + 0];
                    const float f1 = sv[cc * 8 + p2 * 2 + 1];
                    __nv_bfloat16 h0 = __float2bfloat16(f0), h1 = __float2bfloat16(f1);
                    __nv_bfloat162 hp(h0, h1);
                    __nv_bfloat162 lp(__float2bfloat16(f0 - __bfloat162float(h0)),
                                      __float2bfloat16(f1 - __bfloat162float(h1)));
                    wh[p2] = *(uint32_t*)&hp; wl[p2] = *(uint32_t*)&lp;
                }
                const uint32_t so = SW128((uint32_t)(row * 128 + (ch + cc * 8) * 2));
                *(uint4*)(smem + AS_PH + so) = make_uint4(wh[0], wh[1], wh[2], wh[3]);
                *(uint4*)(smem + AS_PL + so) = make_uint4(wl[0], wl[1], wl[2], wl[3]);
            }
            lloc += __shfl_xor_sync(0xffffffffu, lloc, 1);
            __syncwarp();
            if (!(tid & 1)) {
                m_s[row] = mnew; corr_s[row] = corr;
                l_s[row] = l_s[row] * corr + lloc;
            }
        }
        __syncthreads();

        // --- O = O*corr + P @ Vt^T ---
        #pragma unroll
        for (int ms = 0; ms < 2; ms++)
            #pragma unroll
            for (int half = 0; half < 2; half++) {
                const float cc = corr_s[wm * 32 + ms * 16 + (lane >> 2) + half * 8];
                #pragma unroll
                for (int ns = 0; ns < 4; ns++) {
                    O[ms][ns][half * 2 + 0] *= cc;
                    O[ms][ns][half * 2 + 1] *= cc;
                }
            }
        mma_block3(O, sb + AS_PH, sb + AS_PL, stg + 16384, stg + 24576,
                   arow0, akb, brow0, bkb);
        __syncthreads();
    }

    // finalize
    #pragma unroll
    for (int ms = 0; ms < 2; ms++)
        #pragma unroll
        for (int half = 0; half < 2; half++) {
            const int r = wm * 32 + ms * 16 + (lane >> 2) + half * 8;
            const float inv = 1.0f / l_s[r];
            #pragma unroll
            for (int ns = 0; ns < 4; ns++) {
                const int d = wn * 32 + ns * 8 + (lane & 3) * 2;
                *(float2*)(yout + ((size_t)b * T_ + tq0 + r) * C_ + h * D_ + d) =
                    make_float2(O[ms][ns][half * 2] * inv, O[ms][ns][half * 2 + 1] * inv);
            }
        }
}

// ---------------------------------------------------------------------------
extern "C" void kernel_launch(void* const* d_in, const int* in_sizes, int n_in,
                              void* d_out, int out_size)
{
    const float* x    = (const float*)d_in[0];
    const int*   mask = (const int*)  d_in[1];
    const float* rel  = (const float*)d_in[2];
    const float* ref  = (const float*)d_in[3];
    const float* W[6] = {(const float*)d_in[4], (const float*)d_in[6], (const float*)d_in[8],
                         (const float*)d_in[10], (const float*)d_in[12], (const float*)d_in[14]};
    const float* bias[6] = {(const float*)d_in[5], (const float*)d_in[7], (const float*)d_in[9],
                            (const float*)d_in[11], (const float*)d_in[13], (const float*)d_in[15]};
    float* out = (float*)d_out;

    float *qp, *kp, *vp, *yp;
    cudaGetSymbolAddress((void**)&qp, g_q);
    cudaGetSymbolAddress((void**)&kp, g_k);
    cudaGetSymbolAddress((void**)&vp, g_v);
    cudaGetSymbolAddress((void**)&yp, g_y);
    __nv_bfloat16 *xh, *xl, *rh, *rl, *wh, *wl, *yh, *yl, *qh, *ql, *kh, *kl, *vth, *vtl;
    cudaGetSymbolAddress((void**)&xh, g_xh);  cudaGetSymbolAddress((void**)&xl, g_xl);
    cudaGetSymbolAddress((void**)&rh, g_rh);  cudaGetSymbolAddress((void**)&rl, g_rl);
    cudaGetSymbolAddress((void**)&wh, g_wh);  cudaGetSymbolAddress((void**)&wl, g_wl);
    cudaGetSymbolAddress((void**)&yh, g_yh);  cudaGetSymbolAddress((void**)&yl, g_yl);
    cudaGetSymbolAddress((void**)&qh, g_qh);  cudaGetSymbolAddress((void**)&ql, g_ql);
    cudaGetSymbolAddress((void**)&kh, g_kh);  cudaGetSymbolAddress((void**)&kl, g_kl);
    cudaGetSymbolAddress((void**)&vth, g_vth); cudaGetSymbolAddress((void**)&vtl, g_vtl);

    cudaFuncSetAttribute(gemm_mma, cudaFuncAttributeMaxDynamicSharedMemorySize, GSMEM);
    cudaFuncSetAttribute(attn_mma, cudaFuncAttributeMaxDynamicSharedMemorySize, ASMEM);

    const dim3 blk(256);
    const int NX4 = B_ * T_ * C_ / 4, NR4 = B_ * TREF_ * C_ / 4, NW4 = C_ * C_ / 4;
    const int NQ4 = B_ * H_ * T_ * D_ / 4, NK4 = B_ * H_ * SK_ * D_ / 4;
    const dim3 gMain(C_ / 64, (B_ * T_)    / 128);
    const dim3 gRef (C_ / 64, (B_ * TREF_) / 128);
    const size_t WSZ = (size_t)C_ * C_;

    // launch order chosen so launch #5 (profiled by ncu) is gemm_mma (Q proj)
    split_kernel<<<(NX4 + 255) / 256, blk>>>(x,   xh, xl, NX4, 1.f);               // 1
    split_kernel<<<(NW4 + 255) / 256, blk>>>(W[0], wh + 0*WSZ, wl + 0*WSZ, NW4, 1.f); // 2
    split_kernel<<<(NR4 + 255) / 256, blk>>>(ref, rh, rl, NR4, 1.f);               // 3
    split_kernel<<<(NW4 + 255) / 256, blk>>>(W[1], wh + 1*WSZ, wl + 1*WSZ, NW4, 1.f); // 4
    gemm_mma<<<gMain, blk, GSMEM>>>(xh, xl, wh + 0*WSZ, wl + 0*WSZ, bias[0], qp, T_, T_, 0); // 5 (profiled)
    split_kernel<<<(NW4 + 255) / 256, blk>>>(W[2], wh + 2*WSZ, wl + 2*WSZ, NW4, 1.f); // 6
    gemm_mma<<<gMain, blk, GSMEM>>>(xh, xl, wh + 1*WSZ, wl + 1*WSZ, bias[1], kp, T_, SK_, 0);
    split_kernel<<<(NW4 + 255) / 256, blk>>>(W[3], wh + 3*WSZ, wl + 3*WSZ, NW4, 1.f);
    split_kernel<<<(NW4 + 255) / 256, blk>>>(W[4], wh + 4*WSZ, wl + 4*WSZ, NW4, 1.f);
    gemm_mma<<<gMain, blk, GSMEM>>>(xh, xl, wh + 2*WSZ, wl + 2*WSZ, bias[2], vp, T_, SK_, 0);
    gemm_mma<<<gRef,  blk, GSMEM>>>(rh, rl, wh + 3*WSZ, wl + 3*WSZ, bias[3], kp, TREF_, SK_, T_);
    gemm_mma<<<gRef,  blk, GSMEM>>>(rh, rl, wh + 4*WSZ, wl + 4*WSZ, bias[4], vp, TREF_, SK_, T_);

    // attention operand prep: Q scaled by 1/sqrt(D)=0.125 at split time
    split_kernel<<<(NQ4 + 255) / 256, blk>>>(qp, qh, ql, NQ4, 0.125f);
    split_kernel<<<(NK4 + 255) / 256, blk>>>(kp, kh, kl, NK4, 1.f);
    vt_split<<<dim3(SK_ / 64, B_ * H_), blk>>>(vp, vth, vtl);

    attn_mma<<<dim3(T_ / 128, H_, B_), blk, ASMEM>>>(mask, rel, qh, ql, kh, kl, vth, vtl, yp);

    split_kernel<<<(NX4 + 255) / 256, blk>>>(yp, yh, yl, NX4, 1.f);
    split_kernel<<<(NW4 + 255) / 256, blk>>>(W[5], wh + 5*WSZ, wl + 5*WSZ, NW4, 1.f);
    gemm_mma<<<gMain, blk, GSMEM>>>(yh, yl, wh + 5*WSZ, wl + 5*WSZ, bias[5], out, T_, 0, 0);
}

// round 12
// speedup vs baseline: 2.3451x; 1.0114x over previous
#include <cuda_runtime.h>
#include <cuda_bf16.h>
#include <cstdint>
#include <math.h>

#define B_    2
#define T_    2048
#define TREF_ 512
#define C_    768
#define H_    12
#define D_    64
#define SK_   (T_ + TREF_)

__device__ float g_v[(size_t)B_ * H_ * SK_ * D_];
__device__ __nv_bfloat16 g_xh[(size_t)B_ * T_ * C_],    g_xl[(size_t)B_ * T_ * C_];
__device__ __nv_bfloat16 g_rh[(size_t)B_ * TREF_ * C_], g_rl[(size_t)B_ * TREF_ * C_];
__device__ __nv_bfloat16 g_wh[6 * C_ * C_],             g_wl[6 * C_ * C_];
__device__ __nv_bfloat16 g_yh[(size_t)B_ * T_ * C_],    g_yl[(size_t)B_ * T_ * C_];
__device__ __nv_bfloat16 g_qh[(size_t)B_ * H_ * T_  * D_], g_ql[(size_t)B_ * H_ * T_ * D_];
__device__ __nv_bfloat16 g_kh[(size_t)B_ * H_ * SK_ * D_], g_kl[(size_t)B_ * H_ * SK_ * D_];
__device__ __nv_bfloat16 g_vth[(size_t)B_ * H_ * D_ * SK_], g_vtl[(size_t)B_ * H_ * D_ * SK_];

// ---------------- helpers ----------------
__device__ __forceinline__ uint32_t smem_u32(const void* p) {
    uint32_t a;
    asm("{ .reg .u64 t; cvta.to.shared.u64 t, %1; cvt.u32.u64 %0, t; }" : "=r"(a) : "l"(p));
    return a;
}
#define SW128(o) ((o) ^ (((o) >> 3) & 0x70))

__device__ __forceinline__ void ldmx4(uint32_t* r, uint32_t addr) {
    asm volatile("ldmatrix.sync.aligned.m8n8.x4.shared.b16 {%0,%1,%2,%3}, [%4];"
                 : "=r"(r[0]), "=r"(r[1]), "=r"(r[2]), "=r"(r[3]) : "r"(addr));
}
__device__ __forceinline__ void mma_bf16(float* d, const uint32_t* a, const uint32_t* b) {
    asm volatile("mma.sync.aligned.m16n8k16.row.col.f32.bf16.bf16.f32 "
                 "{%0,%1,%2,%3}, {%4,%5,%6,%7}, {%8,%9}, {%0,%1,%2,%3};"
                 : "+f"(d[0]), "+f"(d[1]), "+f"(d[2]), "+f"(d[3])
                 : "r"(a[0]), "r"(a[1]), "r"(a[2]), "r"(a[3]), "r"(b[0]), "r"(b[1]));
}
__device__ __forceinline__ void cp16(uint32_t saddr, const void* g) {
    asm volatile("cp.async.cg.shared.global [%0], [%1], 16;" :: "r"(saddr), "l"(g));
}
#define CP_COMMIT() asm volatile("cp.async.commit_group;" ::: "memory")
#define CP_WAIT(n)  asm volatile("cp.async.wait_group %0;" :: "n"(n) : "memory")

__device__ __forceinline__ void bf16split2(float f0, float f1, uint32_t& hw, uint32_t& lw) {
    __nv_bfloat16 h0 = __float2bfloat16(f0), h1 = __float2bfloat16(f1);
    __nv_bfloat162 hp(h0, h1);
    __nv_bfloat162 lp(__float2bfloat16(f0 - __bfloat162float(h0)),
                      __float2bfloat16(f1 - __bfloat162float(h1)));
    hw = *(uint32_t*)&hp; lw = *(uint32_t*)&lp;
}

// 3-term split-bf16 MMA over one 32x32x64 warp tile (4 ksteps)
__device__ __forceinline__ void mma_block3(float Dv[2][4][4],
    uint32_t baseAh, uint32_t baseAl, uint32_t baseBh, uint32_t baseBl,
    int arow0, uint32_t akb, int brow0, uint32_t bkb)
{
    #pragma unroll
    for (int ks = 0; ks < 4; ks++) {
        uint32_t ah[2][4], al[2][4], bh[2][4], bl[2][4];
        #pragma unroll
        for (int ms = 0; ms < 2; ms++) {
            const uint32_t off = SW128((uint32_t)((arow0 + ms * 16) * 128) + ks * 32 + akb);
            ldmx4(ah[ms], baseAh + off);
            ldmx4(al[ms], baseAl + off);
        }
        #pragma unroll
        for (int nj = 0; nj < 2; nj++) {
            const uint32_t off = SW128((uint32_t)((brow0 + nj * 16) * 128) + ks * 32 + bkb);
            ldmx4(bh[nj], baseBh + off);
            ldmx4(bl[nj], baseBl + off);
        }
        #pragma unroll
        for (int ms = 0; ms < 2; ms++)
            #pragma unroll
            for (int ns = 0; ns < 4; ns++) {
                const uint32_t* fh = &bh[ns >> 1][(ns & 1) * 2];
                const uint32_t* fl = &bl[ns >> 1][(ns & 1) * 2];
                mma_bf16(Dv[ms][ns], ah[ms], fh);
                mma_bf16(Dv[ms][ns], ah[ms], fl);
                mma_bf16(Dv[ms][ns], al[ms], fh);
            }
    }
}

// ---------------- split kernels ----------------
__global__ __launch_bounds__(256)
void split_kernel(const float* __restrict__ src, __nv_bfloat16* __restrict__ hi,
                  __nv_bfloat16* __restrict__ lo, int n4, float scale)
{
    const int i = blockIdx.x * 256 + threadIdx.x;
    if (i >= n4) return;
    const float4 a = ((const float4*)src)[i];
    float av[4] = {a.x * scale, a.y * scale, a.z * scale, a.w * scale};
    uint32_t h0, l0, h1, l1;
    bf16split2(av[0], av[1], h0, l0);
    bf16split2(av[2], av[3], h1, l1);
    ((uint32_t*)hi)[2*i+0] = h0; ((uint32_t*)hi)[2*i+1] = h1;
    ((uint32_t*)lo)[2*i+0] = l0; ((uint32_t*)lo)[2*i+1] = l1;
}

// all 6 weight matrices in one launch (grid.y = 6)
__global__ __launch_bounds__(256)
void split6_kernel(const float* w0, const float* w1, const float* w2,
                   const float* w3, const float* w4, const float* w5,
                   __nv_bfloat16* __restrict__ hi, __nv_bfloat16* __restrict__ lo)
{
    const float* ws[6] = {w0, w1, w2, w3, w4, w5};
    const int wi = blockIdx.y;
    const int i = blockIdx.x * 256 + threadIdx.x;          // n4 per W = C*C/4
    const float4 a = ((const float4*)ws[wi])[i];
    const size_t o = (size_t)wi * (C_ * C_ / 2) + i * 2;   // uint32 units
    uint32_t h0, l0, h1, l1;
    bf16split2(a.x, a.y, h0, l0);
    bf16split2(a.z, a.w, h1, l1);
    ((uint32_t*)hi)[o + 0] = h0; ((uint32_t*)hi)[o + 1] = h1;
    ((uint32_t*)lo)[o + 0] = l0; ((uint32_t*)lo)[o + 1] = l1;
}

// ---------------- V transpose + split ----------------
__global__ __launch_bounds__(256)
void vt_split(const float* __restrict__ v, __nv_bfloat16* __restrict__ vth,
              __nv_bfloat16* __restrict__ vtl)
{
    __shared__ float S[64][68];
    const int bh = blockIdx.y, t0 = blockIdx.x * 64, tid = threadIdx.x;
    const float* src = v + ((size_t)bh * SK_ + t0) * D_;
    #pragma unroll
    for (int it = 0; it < 4; it++) {
        const int u = tid + 256 * it, r = u >> 4, c4 = u & 15;
        *(float4*)&S[r][c4 * 4] = *(const float4*)(src + (size_t)r * D_ + c4 * 4);
    }
    __syncthreads();
    #pragma unroll
    for (int it = 0; it < 2; it++) {
        const int u = tid + 256 * it, d = u >> 3, ch = u & 7;
        uint32_t wh[4], wl[4];
        #pragma unroll
        for (int p = 0; p < 4; p++)
            bf16split2(S[ch * 8 + p * 2 + 0][d], S[ch * 8 + p * 2 + 1][d], wh[p], wl[p]);
        const size_t o = ((size_t)bh * D_ + d) * SK_ + t0 + ch * 8;
        *(uint4*)(vth + o) = make_uint4(wh[0], wh[1], wh[2], wh[3]);
        *(uint4*)(vtl + o) = make_uint4(wl[0], wl[1], wl[2], wl[3]);
    }
}

// ---------------- split-bf16 mma.sync GEMM ----------------
// mode 0: fp32 row-major out (+bias)
// mode 1: fp32 head-scatter out (+bias)
// mode 2: bf16 hi/lo head-scatter (oh/ol), value = (acc+bias)*oscale
#define STSZ  49152
#define GSMEM (2 * STSZ)

__device__ __forceinline__ void cp_stage(uint32_t sbase,
    const __nv_bfloat16* __restrict__ Ah, const __nv_bfloat16* __restrict__ Al,
    const __nv_bfloat16* __restrict__ Bh, const __nv_bfloat16* __restrict__ Bl,
    int m0, int n0, int k0, int tid)
{
    #pragma unroll
    for (int i = 0; i < 4; i++) {
        const int u = tid + 256 * i, r = u >> 3, g = u & 7;
        const size_t go = (size_t)(m0 + r) * C_ + k0 + g * 8;
        const uint32_t so = SW128((uint32_t)(r * 128 + g * 16));
        cp16(sbase + so,         Ah + go);
        cp16(sbase + 16384 + so, Al + go);
    }
    #pragma unroll
    for (int i = 0; i < 2; i++) {
        const int u = tid + 256 * i, r = u >> 3, g = u & 7;
        const size_t go = (size_t)(n0 + r) * C_ + k0 + g * 8;
        const uint32_t so = SW128((uint32_t)(r * 128 + g * 16));
        cp16(sbase + 32768 + so, Bh + go);
        cp16(sbase + 40960 + so, Bl + go);
    }
}

__global__ __launch_bounds__(256)
void gemm_mma(const __nv_bfloat16* __restrict__ Ah, const __nv_bfloat16* __restrict__ Al,
              const __nv_bfloat16* __restrict__ Bh, const __nv_bfloat16* __restrict__ Bl,
              const float* __restrict__ bias, float* __restrict__ out,
              __nv_bfloat16* __restrict__ oh, __nv_bfloat16* __restrict__ ol,
              int Trows, int SKo, int toff, int mode, float oscale)
{
    extern __shared__ char smem[];
    const uint32_t sb = smem_u32(smem);
    const int tid = threadIdx.x, lane = tid & 31, wid = tid >> 5;
    const int wm = wid & 3, wn = wid >> 2;
    const int n0 = blockIdx.x * 64, m0 = blockIdx.y * 128;

    float D[2][4][4] = {};
    cp_stage(sb, Ah, Al, Bh, Bl, m0, n0, 0, tid);
    CP_COMMIT();

    const int arow0 = wm * 32 + (lane & 15);
    const uint32_t akb = ((uint32_t)(lane >> 4)) << 4;
    const int brow0 = wn * 32 + ((lane >> 4) << 3) + (lane & 7);
    const uint32_t bkb = ((uint32_t)((lane >> 3) & 1)) << 4;

    #pragma unroll 1
    for (int c = 0; c < 12; c++) {
        if (c + 1 < 12) {
            cp_stage(sb + ((c + 1) & 1) * STSZ, Ah, Al, Bh, Bl, m0, n0, (c + 1) * 64, tid);
            CP_COMMIT();
            CP_WAIT(1);
        } else CP_WAIT(0);
        __syncthreads();
        const uint32_t bA = sb + (c & 1) * STSZ;
        mma_block3(D, bA, bA + 16384, bA + 32768, bA + 40960, arow0, akb, brow0, bkb);
        __syncthreads();
    }

    const int h = n0 >> 6;
    #pragma unroll
    for (int ns = 0; ns < 4; ns++) {
        const int col = n0 + wn * 32 + ns * 8 + (lane & 3) * 2;
        const float b0 = bias[col], b1 = bias[col + 1];
        #pragma unroll
        for (int ms = 0; ms < 2; ms++) {
            const int r0 = m0 + wm * 32 + ms * 16 + (lane >> 2);
            #pragma unroll
            for (int half = 0; half < 2; half++) {
                const int m = r0 + half * 8;
                float v0 = D[ms][ns][half * 2 + 0] + b0;
                float v1 = D[ms][ns][half * 2 + 1] + b1;
                if (mode == 0) {
                    *(float2*)(out + (size_t)m * C_ + col) = make_float2(v0, v1);
                } else {
                    const int bi = m / Trows, t = m % Trows, d = col - n0;
                    const size_t idx = ((size_t)(bi * H_ + h) * SKo + t + toff) * D_ + d;
                    if (mode == 1) {
                        *(float2*)(out + idx) = make_float2(v0, v1);
                    } else {
                        uint32_t hw, lw;
                        bf16split2(v0 * oscale, v1 * oscale, hw, lw);
                        *(uint32_t*)(oh + idx) = hw;
                        *(uint32_t*)(ol + idx) = lw;
                    }
                }
            }
        }
    }
}

// ---------------- mma.sync flash attention (split-bf16) ----------------
#define AS_QH  0
#define AS_QL  16384
#define AS_STG 32768
#define AS_SS  98304
#define AS_PH  133120
#define AS_PL  149504
#define AS_ST  165888
#define ASMEM  167424

__global__ __launch_bounds__(256)
void attn_mma(const int* __restrict__ mask, const float* __restrict__ rel,
              const __nv_bfloat16* __restrict__ qh, const __nv_bfloat16* __restrict__ ql,
              const __nv_bfloat16* __restrict__ kh, const __nv_bfloat16* __restrict__ kl,
              const __nv_bfloat16* __restrict__ vth, const __nv_bfloat16* __restrict__ vtl,
              __nv_bfloat16* __restrict__ yh, __nv_bfloat16* __restrict__ yl)
{
    extern __shared__ char smem[];
    const uint32_t sb = smem_u32(smem);
    float* Ss     = (float*)(smem + AS_SS);
    float* m_s    = (float*)(smem + AS_ST);
    float* l_s    = m_s + 128;
    float* corr_s = m_s + 256;
    const float NI = __int_as_float(0xff800000);

    const int tid = threadIdx.x, lane = tid & 31, wid = tid >> 5;
    const int wm = wid & 3, wn = wid >> 2;
    const int qb = blockIdx.x, h = blockIdx.y, b = blockIdx.z;
    const int tq0 = qb * 128, bh = b * H_ + h;

    const int arow0 = wm * 32 + (lane & 15);
    const uint32_t akb = ((uint32_t)(lane >> 4)) << 4;
    const int brow0 = wn * 32 + ((lane >> 4) << 3) + (lane & 7);
    const uint32_t bkb = ((uint32_t)((lane >> 3) & 1)) << 4;

    {
        const size_t qbase = ((size_t)bh * T_ + tq0) * D_;
        #pragma unroll
        for (int it = 0; it < 4; it++) {
            const int u = tid + 256 * it, r = u >> 3, g = u & 7;
            const uint32_t so = SW128((uint32_t)(r * 128 + g * 16));
            cp16(sb + AS_QH + so, qh + qbase + (size_t)r * D_ + g * 8);
            cp16(sb + AS_QL + so, ql + qbase + (size_t)r * D_ + g * 8);
        }
        const size_t kbase = (size_t)bh * SK_ * D_;
        const size_t vbase = (size_t)bh * D_ * SK_;
        #pragma unroll
        for (int it = 0; it < 2; it++) {
            const int u = tid + 256 * it, r = u >> 3, g = u & 7;
            const uint32_t so = SW128((uint32_t)(r * 128 + g * 16));
            cp16(sb + AS_STG + so,         kh + kbase + (size_t)r * D_ + g * 8);
            cp16(sb + AS_STG + 8192 + so,  kl + kbase + (size_t)r * D_ + g * 8);
            cp16(sb + AS_STG + 16384 + so, vth + vbase + (size_t)r * SK_ + g * 8);
            cp16(sb + AS_STG + 24576 + so, vtl + vbase + (size_t)r * SK_ + g * 8);
        }
        CP_COMMIT();
    }
    if (tid < 128) { m_s[tid] = NI; l_s[tid] = 0.f; }
    float O[2][4][4] = {};

    #pragma unroll 1
    for (int kb = 0; kb < SK_ / 64; kb++) {
        if (kb + 1 < SK_ / 64) {
            const uint32_t st = sb + AS_STG + ((kb + 1) & 1) * 32768;
            const size_t kbase = ((size_t)bh * SK_ + (kb + 1) * 64) * D_;
            const size_t vbase = (size_t)bh * D_ * SK_ + (kb + 1) * 64;
            #pragma unroll
            for (int it = 0; it < 2; it++) {
                const int u = tid + 256 * it, r = u >> 3, g = u & 7;
                const uint32_t so = SW128((uint32_t)(r * 128 + g * 16));
                cp16(st + so,         kh + kbase + (size_t)r * D_ + g * 8);
                cp16(st + 8192 + so,  kl + kbase + (size_t)r * D_ + g * 8);
                cp16(st + 16384 + so, vth + vbase + (size_t)r * SK_ + g * 8);
                cp16(st + 24576 + so, vtl + vbase + (size_t)r * SK_ + g * 8);
            }
            CP_COMMIT();
            CP_WAIT(1);
        } else CP_WAIT(0);
        __syncthreads();

        const uint32_t stg = sb + AS_STG + (kb & 1) * 32768;

        float Dq[2][4][4] = {};
        mma_block3(Dq, sb + AS_QH, sb + AS_QL, stg, stg + 8192, arow0, akb, brow0, bkb);

        #pragma unroll
        for (int ms = 0; ms < 2; ms++)
            #pragma unroll
            for (int ns = 0; ns < 4; ns++) {
                const int col = wn * 32 + ns * 8 + (lane & 3) * 2;
                #pragma unroll
                for (int half = 0; half < 2; half++) {
                    const int r = wm * 32 + ms * 16 + (lane >> 2) + half * 8;
                    *(float2*)&Ss[r * 68 + col] =
                        make_float2(Dq[ms][ns][half * 2], Dq[ms][ns][half * 2 + 1]);
                }
            }
        __syncthreads();

        {
            const int row = tid >> 1, ch = (tid & 1) * 32;
            float sv[32];
            if (kb < T_ / 64) {
                const int tq = tq0 + row;
                const int*   mp = mask + ((size_t)b * T_ + tq) * T_ + kb * 64 + ch;
                const float* rp = rel  + ((size_t)h * T_ + tq) * T_ + kb * 64 + ch;
                #pragma unroll
                for (int j = 0; j < 8; j++) {
                    const int4   mv = *(const int4*)(mp + j * 4);
                    const float4 rv = *(const float4*)(rp + j * 4);
                    const float4 s  = *(const float4*)&Ss[row * 68 + ch + j * 4];
                    sv[j*4+0] = (mv.x == 1) ? NI : s.x + rv.x;
                    sv[j*4+1] = (mv.y == 1) ? NI : s.y + rv.y;
                    sv[j*4+2] = (mv.z == 1) ? NI : s.z + rv.z;
                    sv[j*4+3] = (mv.w == 1) ? NI : s.w + rv.w;
                }
            } else {
                #pragma unroll
                for (int j = 0; j < 8; j++) {
                    const float4 s = *(const float4*)&Ss[row * 68 + ch + j * 4];
                    sv[j*4+0] = s.x; sv[j*4+1] = s.y; sv[j*4+2] = s.z; sv[j*4+3] = s.w;
                }
            }
            float mloc = NI;
            #pragma unroll
            for (int j = 0; j < 32; j++) mloc = fmaxf(mloc, sv[j]);
            mloc = fmaxf(mloc, __shfl_xor_sync(0xffffffffu, mloc, 1));
            const float mold = m_s[row];
            const float mnew = fmaxf(mold, mloc);
            const float corr = (mold == NI) ? 0.f : __expf(mold - mnew);
            float lloc = 0.f;
            #pragma unroll
            for (int j = 0; j < 32; j++) {
                const float p = (sv[j] == NI) ? 0.f : __expf(sv[j] - mnew);
                sv[j] = p; lloc += p;
            }
            #pragma unroll
            for (int cc = 0; cc < 4; cc++) {
                uint32_t wh[4], wl[4];
                #pragma unroll
                for (int p2 = 0; p2 < 4; p2++)
                    bf16split2(sv[cc * 8 + p2 * 2], sv[cc * 8 + p2 * 2 + 1], wh[p2], wl[p2]);
                const uint32_t so = SW128((uint32_t)(row * 128 + (ch + cc * 8) * 2));
                *(uint4*)(smem + AS_PH + so) = make_uint4(wh[0], wh[1], wh[2], wh[3]);
                *(uint4*)(smem + AS_PL + so) = make_uint4(wl[0], wl[1], wl[2], wl[3]);
            }
            lloc += __shfl_xor_sync(0xffffffffu, lloc, 1);
            __syncwarp();
            if (!(tid & 1)) {
                m_s[row] = mnew; corr_s[row] = corr;
                l_s[row] = l_s[row] * corr + lloc;
            }
        }
        __syncthreads();

        #pragma unroll
        for (int ms = 0; ms < 2; ms++)
            #pragma unroll
            for (int half = 0; half < 2; half++) {
                const float cc = corr_s[wm * 32 + ms * 16 + (lane >> 2) + half * 8];
                #pragma unroll
                for (int ns = 0; ns < 4; ns++) {
                    O[ms][ns][half * 2 + 0] *= cc;
                    O[ms][ns][half * 2 + 1] *= cc;
                }
            }
        mma_block3(O, sb + AS_PH, sb + AS_PL, stg + 16384, stg + 24576,
                   arow0, akb, brow0, bkb);
        __syncthreads();
    }

    // finalize: write y as bf16 hi/lo directly
    #pragma unroll
    for (int ms = 0; ms < 2; ms++)
        #pragma unroll
        for (int half = 0; half < 2; half++) {
            const int r = wm * 32 + ms * 16 + (lane >> 2) + half * 8;
            const float inv = 1.0f / l_s[r];
            #pragma unroll
            for (int ns = 0; ns < 4; ns++) {
                const int d = wn * 32 + ns * 8 + (lane & 3) * 2;
                const size_t idx = ((size_t)b * T_ + tq0 + r) * C_ + h * D_ + d;
                uint32_t hw, lw;
                bf16split2(O[ms][ns][half * 2] * inv, O[ms][ns][half * 2 + 1] * inv, hw, lw);
                *(uint32_t*)(yh + idx) = hw;
                *(uint32_t*)(yl + idx) = lw;
            }
        }
}

// ---------------------------------------------------------------------------
extern "C" void kernel_launch(void* const* d_in, const int* in_sizes, int n_in,
                              void* d_out, int out_size)
{
    const float* x    = (const float*)d_in[0];
    const int*   mask = (const int*)  d_in[1];
    const float* rel  = (const float*)d_in[2];
    const float* ref  = (const float*)d_in[3];
    const float* W[6] = {(const float*)d_in[4], (const float*)d_in[6], (const float*)d_in[8],
                         (const float*)d_in[10], (const float*)d_in[12], (const float*)d_in[14]};
    const float* bias[6] = {(const float*)d_in[5], (const float*)d_in[7], (const float*)d_in[9],
                            (const float*)d_in[11], (const float*)d_in[13], (const float*)d_in[15]};
    float* out = (float*)d_out;

    float* vp;
    cudaGetSymbolAddress((void**)&vp, g_v);
    __nv_bfloat16 *xh, *xl, *rh, *rl, *wh, *wl, *yh, *yl, *qh, *ql, *kh, *kl, *vth, *vtl;
    cudaGetSymbolAddress((void**)&xh, g_xh);  cudaGetSymbolAddress((void**)&xl, g_xl);
    cudaGetSymbolAddress((void**)&rh, g_rh);  cudaGetSymbolAddress((void**)&rl, g_rl);
    cudaGetSymbolAddress((void**)&wh, g_wh);  cudaGetSymbolAddress((void**)&wl, g_wl);
    cudaGetSymbolAddress((void**)&yh, g_yh);  cudaGetSymbolAddress((void**)&yl, g_yl);
    cudaGetSymbolAddress((void**)&qh, g_qh);  cudaGetSymbolAddress((void**)&ql, g_ql);
    cudaGetSymbolAddress((void**)&kh, g_kh);  cudaGetSymbolAddress((void**)&kl, g_kl);
    cudaGetSymbolAddress((void**)&vth, g_vth); cudaGetSymbolAddress((void**)&vtl, g_vtl);

    cudaFuncSetAttribute(gemm_mma, cudaFuncAttributeMaxDynamicSharedMemorySize, GSMEM);
    cudaFuncSetAttribute(attn_mma, cudaFuncAttributeMaxDynamicSharedMemorySize, ASMEM);

    const dim3 blk(256);
    const int NX4 = B_ * T_ * C_ / 4, NR4 = B_ * TREF_ * C_ / 4, NW4 = C_ * C_ / 4;
    const dim3 gMain(C_ / 64, (B_ * T_)    / 128);
    const dim3 gRef (C_ / 64, (B_ * TREF_) / 128);
    const size_t WSZ = (size_t)C_ * C_;

    // 1-3: operand splits
    split_kernel<<<(NX4 + 255) / 256, blk>>>(x,   xh, xl, NX4, 1.f);
    split6_kernel<<<dim3((NW4 + 255) / 256, 6), blk>>>(W[0], W[1], W[2], W[3], W[4], W[5], wh, wl);
    split_kernel<<<(NR4 + 255) / 256, blk>>>(ref, rh, rl, NR4, 1.f);
    // 4: Q proj -> bf16 hi/lo, pre-scaled
    gemm_mma<<<gMain, blk, GSMEM>>>(xh, xl, wh + 0*WSZ, wl + 0*WSZ, bias[0],
                                    nullptr, qh, ql, T_, T_, 0, 2, 0.125f);
    // 5: K proj -> bf16 hi/lo
    gemm_mma<<<gMain, blk, GSMEM>>>(xh, xl, wh + 1*WSZ, wl + 1*WSZ, bias[1],
                                    nullptr, kh, kl, T_, SK_, 0, 2, 1.f);
    // 6: V proj -> fp32 scatter  (PROFILED LAUNCH)
    gemm_mma<<<gMain, blk, GSMEM>>>(xh, xl, wh + 2*WSZ, wl + 2*WSZ, bias[2],
                                    vp, nullptr, nullptr, T_, SK_, 0, 1, 1.f);
    // 7-8: ref projections
    gemm_mma<<<gRef, blk, GSMEM>>>(rh, rl, wh + 3*WSZ, wl + 3*WSZ, bias[3],
                                   nullptr, kh, kl, TREF_, SK_, T_, 2, 1.f);
    gemm_mma<<<gRef, blk, GSMEM>>>(rh, rl, wh + 4*WSZ, wl + 4*WSZ, bias[4],
                                   vp, nullptr, nullptr, TREF_, SK_, T_, 1, 1.f);
    // 9: V transpose+split
    vt_split<<<dim3(SK_ / 64, B_ * H_), blk>>>(vp, vth, vtl);
    // 10: attention -> yh/yl
    attn_mma<<<dim3(T_ / 128, H_, B_), blk, ASMEM>>>(mask, rel, qh, ql, kh, kl, vth, vtl, yh, yl);
    // 11: output projection
    gemm_mma<<<gMain, blk, GSMEM>>>(yh, yl, wh + 5*WSZ, wl + 5*WSZ, bias[5],
                                    out, nullptr, nullptr, T_, 0, 0, 0, 1.f);
}

// round 14
// speedup vs baseline: 2.5038x; 1.0676x over previous
#include <cuda_runtime.h>
#include <cuda_bf16.h>
#include <cstdint>
#include <math.h>

#define B_    2
#define T_    2048
#define TREF_ 512
#define C_    768
#define H_    12
#define D_    64
#define SK_   (T_ + TREF_)
#define L2E   1.4426950408889634f
#define QSC   (0.125f * L2E)

__device__ __nv_bfloat16 g_xh[(size_t)B_ * T_ * C_],    g_xl[(size_t)B_ * T_ * C_];
__device__ __nv_bfloat16 g_rh[(size_t)B_ * TREF_ * C_], g_rl[(size_t)B_ * TREF_ * C_];
__device__ __nv_bfloat16 g_wh[6 * C_ * C_],             g_wl[6 * C_ * C_];
__device__ __nv_bfloat16 g_yh[(size_t)B_ * T_ * C_],    g_yl[(size_t)B_ * T_ * C_];
__device__ __nv_bfloat16 g_qh[(size_t)B_ * H_ * T_  * D_], g_ql[(size_t)B_ * H_ * T_ * D_];
__device__ __nv_bfloat16 g_kh[(size_t)B_ * H_ * SK_ * D_], g_kl[(size_t)B_ * H_ * SK_ * D_];
__device__ __nv_bfloat16 g_vth[(size_t)B_ * H_ * D_ * SK_], g_vtl[(size_t)B_ * H_ * D_ * SK_];

// ---------------- helpers ----------------
__device__ __forceinline__ uint32_t smem_u32(const void* p) {
    uint32_t a;
    asm("{ .reg .u64 t; cvta.to.shared.u64 t, %1; cvt.u32.u64 %0, t; }" : "=r"(a) : "l"(p));
    return a;
}
#define SW128(o) ((o) ^ (((o) >> 3) & 0x70))

__device__ __forceinline__ void ldmx4(uint32_t* r, uint32_t addr) {
    asm volatile("ldmatrix.sync.aligned.m8n8.x4.shared.b16 {%0,%1,%2,%3}, [%4];"
                 : "=r"(r[0]), "=r"(r[1]), "=r"(r[2]), "=r"(r[3]) : "r"(addr));
}
__device__ __forceinline__ void mma_bf16(float* d, const uint32_t* a, const uint32_t* b) {
    asm volatile("mma.sync.aligned.m16n8k16.row.col.f32.bf16.bf16.f32 "
                 "{%0,%1,%2,%3}, {%4,%5,%6,%7}, {%8,%9}, {%0,%1,%2,%3};"
                 : "+f"(d[0]), "+f"(d[1]), "+f"(d[2]), "+f"(d[3])
                 : "r"(a[0]), "r"(a[1]), "r"(a[2]), "r"(a[3]), "r"(b[0]), "r"(b[1]));
}
__device__ __forceinline__ void cp16(uint32_t saddr, const void* g) {
    asm volatile("cp.async.cg.shared.global [%0], [%1], 16;" :: "r"(saddr), "l"(g));
}
#define CP_COMMIT() asm volatile("cp.async.commit_group;" ::: "memory")
#define CP_WAIT(n)  asm volatile("cp.async.wait_group %0;" :: "n"(n) : "memory")

__device__ __forceinline__ float ex2(float x) {
    float r;
    asm("ex2.approx.f32 %0, %1;" : "=f"(r) : "f"(x));
    return r;
}
__device__ __forceinline__ void bf16split2(float f0, float f1, uint32_t& hw, uint32_t& lw) {
    __nv_bfloat16 h0 = __float2bfloat16(f0), h1 = __float2bfloat16(f1);
    __nv_bfloat162 hp(h0, h1);
    __nv_bfloat162 lp(__float2bfloat16(f0 - __bfloat162float(h0)),
                      __float2bfloat16(f1 - __bfloat162float(h1)));
    hw = *(uint32_t*)&hp; lw = *(uint32_t*)&lp;
}

// ---------------- fused x+ref split ----------------
#define NX4 (B_ * T_ * C_ / 4)
#define NR4 (B_ * TREF_ * C_ / 4)
__global__ __launch_bounds__(256)
void splitXR(const float* __restrict__ x, const float* __restrict__ ref,
             __nv_bfloat16* __restrict__ xh, __nv_bfloat16* __restrict__ xl,
             __nv_bfloat16* __restrict__ rh, __nv_bfloat16* __restrict__ rl)
{
    const int bx = blockIdx.x;
    const float* src; __nv_bfloat16 *hi, *lo; int i;
    if (bx < NX4 / 256) { src = x;   hi = xh; lo = xl; i = bx * 256 + threadIdx.x; }
    else                { src = ref; hi = rh; lo = rl; i = (bx - NX4 / 256) * 256 + threadIdx.x; }
    const float4 a = ((const float4*)src)[i];
    uint32_t h0, l0, h1, l1;
    bf16split2(a.x, a.y, h0, l0);
    bf16split2(a.z, a.w, h1, l1);
    ((uint32_t*)hi)[2*i+0] = h0; ((uint32_t*)hi)[2*i+1] = h1;
    ((uint32_t*)lo)[2*i+0] = l0; ((uint32_t*)lo)[2*i+1] = l1;
}

__global__ __launch_bounds__(256)
void split6_kernel(const float* w0, const float* w1, const float* w2,
                   const float* w3, const float* w4, const float* w5,
                   __nv_bfloat16* __restrict__ hi, __nv_bfloat16* __restrict__ lo)
{
    const float* ws[6] = {w0, w1, w2, w3, w4, w5};
    const int wi = blockIdx.y;
    const int i = blockIdx.x * 256 + threadIdx.x;
    const float4 a = ((const float4*)ws[wi])[i];
    const size_t o = (size_t)wi * (C_ * C_ / 2) + i * 2;
    uint32_t h0, l0, h1, l1;
    bf16split2(a.x, a.y, h0, l0);
    bf16split2(a.z, a.w, h1, l1);
    ((uint32_t*)hi)[o + 0] = h0; ((uint32_t*)hi)[o + 1] = h1;
    ((uint32_t*)lo)[o + 0] = l0; ((uint32_t*)lo)[o + 1] = l1;
}

// ---------------- split-bf16 mma.sync GEMM (segmented, 3 epilogues) --------
// mode 0: fp32 row-major out (+bias)
// mode 2: bf16 hi/lo head-scatter (oh/ol), value = (acc+bias)*oscale
// mode 3: transpose-split epilogue -> vth/vtl [bh][d][key]
#define STSZ  49152
#define GSMEM (2 * STSZ)

__device__ __forceinline__ void cp_stage(uint32_t sbase,
    const __nv_bfloat16* __restrict__ Ah, const __nv_bfloat16* __restrict__ Al,
    const __nv_bfloat16* __restrict__ Bh, const __nv_bfloat16* __restrict__ Bl,
    int m0, int n0, int k0, int tid)
{
    #pragma unroll
    for (int i = 0; i < 4; i++) {
        const int u = tid + 256 * i, r = u >> 3, g = u & 7;
        const size_t go = (size_t)(m0 + r) * C_ + k0 + g * 8;
        const uint32_t so = SW128((uint32_t)(r * 128 + g * 16));
        cp16(sbase + so,         Ah + go);
        cp16(sbase + 16384 + so, Al + go);
    }
    #pragma unroll
    for (int i = 0; i < 2; i++) {
        const int u = tid + 256 * i, r = u >> 3, g = u & 7;
        const size_t go = (size_t)(n0 + r) * C_ + k0 + g * 8;
        const uint32_t so = SW128((uint32_t)(r * 128 + g * 16));
        cp16(sbase + 32768 + so, Bh + go);
        cp16(sbase + 40960 + so, Bl + go);
    }
}

__device__ __forceinline__ void mma_block3(float Dv[2][4][4],
    uint32_t baseAh, uint32_t baseAl, uint32_t baseBh, uint32_t baseBl,
    int arow0, uint32_t akb, int brow0, uint32_t bkb)
{
    #pragma unroll
    for (int ks = 0; ks < 4; ks++) {
        uint32_t ah[2][4], al[2][4], bh[2][4], bl[2][4];
        #pragma unroll
        for (int ms = 0; ms < 2; ms++) {
            const uint32_t off = SW128((uint32_t)((arow0 + ms * 16) * 128) + ks * 32 + akb);
            ldmx4(ah[ms], baseAh + off);
            ldmx4(al[ms], baseAl + off);
        }
        #pragma unroll
        for (int nj = 0; nj < 2; nj++) {
            const uint32_t off = SW128((uint32_t)((brow0 + nj * 16) * 128) + ks * 32 + bkb);
            ldmx4(bh[nj], baseBh + off);
            ldmx4(bl[nj], baseBl + off);
        }
        #pragma unroll
        for (int ms = 0; ms < 2; ms++)
            #pragma unroll
            for (int ns = 0; ns < 4; ns++) {
                const uint32_t* fh = &bh[ns >> 1][(ns & 1) * 2];
                const uint32_t* fl = &bl[ns >> 1][(ns & 1) * 2];
                mma_bf16(Dv[ms][ns], ah[ms], fh);
                mma_bf16(Dv[ms][ns], ah[ms], fl);
                mma_bf16(Dv[ms][ns], al[ms], fh);
            }
    }
}

__global__ __launch_bounds__(256)
void gemm_mma(const __nv_bfloat16* Ah0, const __nv_bfloat16* Al0,
              const __nv_bfloat16* Wh0, const __nv_bfloat16* Wl0, const float* bias0,
              const __nv_bfloat16* Ah1, const __nv_bfloat16* Al1,
              const __nv_bfloat16* Wh1, const __nv_bfloat16* Wl1, const float* bias1,
              int splitY, int Trows0, int toff0, int Trows1, int toff1,
              int SKo, int mode, float oscale,
              float* out, __nv_bfloat16* oh, __nv_bfloat16* ol)
{
    extern __shared__ char smem[];
    const uint32_t sb = smem_u32(smem);
    const int tid = threadIdx.x, lane = tid & 31, wid = tid >> 5;
    const int wm = wid & 3, wn = wid >> 2;
    const int by = blockIdx.y;
    const bool segB = by >= splitY;
    const __nv_bfloat16* Ah = segB ? Ah1 : Ah0;
    const __nv_bfloat16* Al = segB ? Al1 : Al0;
    const __nv_bfloat16* Wh = segB ? Wh1 : Wh0;
    const __nv_bfloat16* Wl = segB ? Wl1 : Wl0;
    const float* bias = segB ? bias1 : bias0;
    const int Trows = segB ? Trows1 : Trows0;
    const int toff  = segB ? toff1  : toff0;
    const int n0 = blockIdx.x * 64;
    const int m0 = (segB ? (by - splitY) : by) * 128;

    float D[2][4][4] = {};
    cp_stage(sb, Ah, Al, Wh, Wl, m0, n0, 0, tid);
    CP_COMMIT();

    const int arow0 = wm * 32 + (lane & 15);
    const uint32_t akb = ((uint32_t)(lane >> 4)) << 4;
    const int brow0 = wn * 32 + ((lane >> 4) << 3) + (lane & 7);
    const uint32_t bkb = ((uint32_t)((lane >> 3) & 1)) << 4;

    #pragma unroll 1
    for (int c = 0; c < 12; c++) {
        if (c + 1 < 12) {
            cp_stage(sb + ((c + 1) & 1) * STSZ, Ah, Al, Wh, Wl, m0, n0, (c + 1) * 64, tid);
            CP_COMMIT();
            CP_WAIT(1);
        } else CP_WAIT(0);
        __syncthreads();
        const uint32_t bA = sb + (c & 1) * STSZ;
        mma_block3(D, bA, bA + 16384, bA + 32768, bA + 40960, arow0, akb, brow0, bkb);
        __syncthreads();
    }

    const int h = n0 >> 6;
    if (mode == 3) {
        // stage (token x d) fp32 tile, then transpose-split to vth/vtl[bh][d][key]
        float* S = (float*)smem;                      // 128 x 68
        #pragma unroll
        for (int ns = 0; ns < 4; ns++) {
            const int col = wn * 32 + ns * 8 + (lane & 3) * 2;
            const float b0 = bias[n0 + col], b1 = bias[n0 + col + 1];
            #pragma unroll
            for (int ms = 0; ms < 2; ms++)
                #pragma unroll
                for (int half = 0; half < 2; half++) {
                    const int r = wm * 32 + ms * 16 + (lane >> 2) + half * 8;
                    *(float2*)&S[r * 68 + col] =
                        make_float2(D[ms][ns][half*2] + b0, D[ms][ns][half*2+1] + b1);
                }
        }
        __syncthreads();
        const int bi = m0 / Trows, t0 = m0 % Trows;
        const int bh = bi * H_ + h;
        #pragma unroll
        for (int it = 0; it < 4; it++) {
            const int u = tid + 256 * it, d = u >> 4, ch = u & 15;
            float f[8];
            #pragma unroll
            for (int p = 0; p < 8; p++) f[p] = S[(ch * 8 + p) * 68 + d];
            uint32_t hw[4], lw[4];
            #pragma unroll
            for (int p = 0; p < 4; p++) bf16split2(f[2*p], f[2*p+1], hw[p], lw[p]);
            const size_t o = ((size_t)bh * D_ + d) * SK_ + toff + t0 + ch * 8;
            *(uint4*)(oh + o) = make_uint4(hw[0], hw[1], hw[2], hw[3]);
            *(uint4*)(ol + o) = make_uint4(lw[0], lw[1], lw[2], lw[3]);
        }
    } else {
        #pragma unroll
        for (int ns = 0; ns < 4; ns++) {
            const int col = n0 + wn * 32 + ns * 8 + (lane & 3) * 2;
            const float b0 = bias[col], b1 = bias[col + 1];
            #pragma unroll
            for (int ms = 0; ms < 2; ms++) {
                const int r0 = m0 + wm * 32 + ms * 16 + (lane >> 2);
                #pragma unroll
                for (int half = 0; half < 2; half++) {
                    const int m = r0 + half * 8;
                    const float v0 = D[ms][ns][half*2+0] + b0;
                    const float v1 = D[ms][ns][half*2+1] + b1;
                    if (mode == 0) {
                        *(float2*)(out + (size_t)m * C_ + col) = make_float2(v0, v1);
                    } else {
                        const int bi = m / Trows, t = m % Trows, d = col - n0;
                        const size_t idx = ((size_t)(bi * H_ + h) * SKo + t + toff) * D_ + d;
                        uint32_t hw, lw;
                        bf16split2(v0 * oscale, v1 * oscale, hw, lw);
                        *(uint32_t*)(oh + idx) = hw;
                        *(uint32_t*)(ol + idx) = lw;
                    }
                }
            }
        }
    }
}

// ---------------- register-softmax mma.sync flash attention ----------------
// 8 warps x (16 rows x 64 keys). Q in smem; K/V double-buffered; S/P in regs.
#define AS_QH  0
#define AS_QL  16384
#define AS_STG 32768           /* +s*32768: KH | KL +8192 | VTH +16384 | VTL +24576 */
#define ASMEM  (32768 + 2 * 32768)

__global__ __launch_bounds__(256)
void attn_mma(const int* __restrict__ mask, const float* __restrict__ rel,
              const __nv_bfloat16* __restrict__ qh, const __nv_bfloat16* __restrict__ ql,
              const __nv_bfloat16* __restrict__ kh, const __nv_bfloat16* __restrict__ kl,
              const __nv_bfloat16* __restrict__ vth, const __nv_bfloat16* __restrict__ vtl,
              __nv_bfloat16* __restrict__ yh, __nv_bfloat16* __restrict__ yl)
{
    extern __shared__ char smem[];
    const uint32_t sb = smem_u32(smem);
    const float NI = __int_as_float(0xff800000);

    const int tid = threadIdx.x, lane = tid & 31, wid = tid >> 5;
    const int qb = blockIdx.x, hh = blockIdx.y, bb = blockIdx.z;
    const int tq0 = qb * 128, bh = bb * H_ + hh;
    const int r0g = tq0 + wid * 16 + (lane >> 2);    // global row of this lane (and +8)

    // initial loads: Q (persist) + stage 0
    {
        const size_t qbase = ((size_t)bh * T_ + tq0) * D_;
        #pragma unroll
        for (int it = 0; it < 4; it++) {
            const int u = tid + 256 * it, r = u >> 3, g = u & 7;
            const uint32_t so = SW128((uint32_t)(r * 128 + g * 16));
            cp16(sb + AS_QH + so, qh + qbase + (size_t)r * D_ + g * 8);
            cp16(sb + AS_QL + so, ql + qbase + (size_t)r * D_ + g * 8);
        }
        const size_t kbase = (size_t)bh * SK_ * D_;
        const size_t vbase = (size_t)bh * D_ * SK_;
        #pragma unroll
        for (int it = 0; it < 2; it++) {
            const int u = tid + 256 * it, r = u >> 3, g = u & 7;
            const uint32_t so = SW128((uint32_t)(r * 128 + g * 16));
            cp16(sb + AS_STG + so,         kh + kbase + (size_t)r * D_ + g * 8);
            cp16(sb + AS_STG + 8192 + so,  kl + kbase + (size_t)r * D_ + g * 8);
            cp16(sb + AS_STG + 16384 + so, vth + vbase + (size_t)r * SK_ + g * 8);
            cp16(sb + AS_STG + 24576 + so, vtl + vbase + (size_t)r * SK_ + g * 8);
        }
        CP_COMMIT();
    }

    float O[8][4] = {};
    float mp0 = NI, mp1 = NI, l0 = 0.f, l1 = 0.f;

    #pragma unroll 1
    for (int kb = 0; kb < SK_ / 64; kb++) {
        if (kb + 1 < SK_ / 64) {
            const uint32_t st = sb + AS_STG + ((kb + 1) & 1) * 32768;
            const size_t kbase = ((size_t)bh * SK_ + (kb + 1) * 64) * D_;
            const size_t vbase = (size_t)bh * D_ * SK_ + (kb + 1) * 64;
            #pragma unroll
            for (int it = 0; it < 2; it++) {
                const int u = tid + 256 * it, r = u >> 3, g = u & 7;
                const uint32_t so = SW128((uint32_t)(r * 128 + g * 16));
                cp16(st + so,         kh + kbase + (size_t)r * D_ + g * 8);
                cp16(st + 8192 + so,  kl + kbase + (size_t)r * D_ + g * 8);
                cp16(st + 16384 + so, vth + vbase + (size_t)r * SK_ + g * 8);
                cp16(st + 24576 + so, vtl + vbase + (size_t)r * SK_ + g * 8);
            }
            CP_COMMIT();
            CP_WAIT(1);
        } else CP_WAIT(0);
        __syncthreads();

        const uint32_t stg = sb + AS_STG + (kb & 1) * 32768;

        // ---- QK: Dq[8 n-tiles][4] over 64 keys, 3-term split ----
        float Dq[8][4];
        #pragma unroll
        for (int ns = 0; ns < 8; ns++)
            Dq[ns][0] = Dq[ns][1] = Dq[ns][2] = Dq[ns][3] = 0.f;
        #pragma unroll
        for (int ks = 0; ks < 4; ks++) {
            uint32_t qfh[4], qfl[4];
            const uint32_t qoff =
                SW128((uint32_t)((wid * 16 + (lane & 15)) * 128) + ks * 32 + (((uint32_t)(lane >> 4)) << 4));
            ldmx4(qfh, sb + AS_QH + qoff);
            ldmx4(qfl, sb + AS_QL + qoff);
            uint32_t kfh[4][4], kfl[4][4];
            #pragma unroll
            for (int nj = 0; nj < 4; nj++) {
                const uint32_t off =
                    SW128((uint32_t)((nj * 16 + ((lane >> 4) << 3) + (lane & 7)) * 128) + ks * 32 +
                          (((uint32_t)((lane >> 3) & 1)) << 4));
                ldmx4(kfh[nj], stg + off);
                ldmx4(kfl[nj], stg + 8192 + off);
            }
            #pragma unroll
            for (int ns = 0; ns < 8; ns++) {
                const uint32_t* fh = &kfh[ns >> 1][(ns & 1) * 2];
                const uint32_t* fl = &kfl[ns >> 1][(ns & 1) * 2];
                mma_bf16(Dq[ns], qfh, fh);
                mma_bf16(Dq[ns], qfh, fl);
                mma_bf16(Dq[ns], qfl, fh);
            }
        }

        // ---- bias (mask/rel) in-register ----
        if (kb < T_ / 64) {
            const int colb = kb * 64 + (lane & 3) * 2;
            const size_t mrow0 = ((size_t)bb * T_ + r0g) * T_ + colb;
            const size_t rrow0 = ((size_t)hh * T_ + r0g) * T_ + colb;
            #pragma unroll
            for (int ns = 0; ns < 8; ns++) {
                const int o = ns * 8;
                const int2   mv0 = *(const int2*)  (mask + mrow0 + o);
                const float2 rv0 = *(const float2*)(rel  + rrow0 + o);
                Dq[ns][0] = mv0.x ? NI : fmaf(rv0.x, L2E, Dq[ns][0]);
                Dq[ns][1] = mv0.y ? NI : fmaf(rv0.y, L2E, Dq[ns][1]);
                const int2   mv1 = *(const int2*)  (mask + mrow0 + (size_t)8 * T_ + o);
                const float2 rv1 = *(const float2*)(rel  + rrow0 + (size_t)8 * T_ + o);
                Dq[ns][2] = mv1.x ? NI : fmaf(rv1.x, L2E, Dq[ns][2]);
                Dq[ns][3] = mv1.y ? NI : fmaf(rv1.y, L2E, Dq[ns][3]);
            }
        }

        // ---- online softmax in registers (quad-lane reductions) ----
        float m0l = NI, m1l = NI;
        #pragma unroll
        for (int ns = 0; ns < 8; ns++) {
            m0l = fmaxf(m0l, fmaxf(Dq[ns][0], Dq[ns][1]));
            m1l = fmaxf(m1l, fmaxf(Dq[ns][2], Dq[ns][3]));
        }
        m0l = fmaxf(m0l, __shfl_xor_sync(0xffffffffu, m0l, 1));
        m0l = fmaxf(m0l, __shfl_xor_sync(0xffffffffu, m0l, 2));
        m1l = fmaxf(m1l, __shfl_xor_sync(0xffffffffu, m1l, 1));
        m1l = fmaxf(m1l, __shfl_xor_sync(0xffffffffu, m1l, 2));
        const float mn0 = fmaxf(mp0, m0l), mn1 = fmaxf(mp1, m1l);
        const float c0 = (mp0 == NI) ? 0.f : ex2(mp0 - mn0);
        const float c1 = (mp1 == NI) ? 0.f : ex2(mp1 - mn1);
        float s0 = 0.f, s1 = 0.f;
        #pragma unroll
        for (int ns = 0; ns < 8; ns++) {
            float p;
            p = (Dq[ns][0] == NI) ? 0.f : ex2(Dq[ns][0] - mn0); Dq[ns][0] = p; s0 += p;
            p = (Dq[ns][1] == NI) ? 0.f : ex2(Dq[ns][1] - mn0); Dq[ns][1] = p; s0 += p;
            p = (Dq[ns][2] == NI) ? 0.f : ex2(Dq[ns][2] - mn1); Dq[ns][2] = p; s1 += p;
            p = (Dq[ns][3] == NI) ? 0.f : ex2(Dq[ns][3] - mn1); Dq[ns][3] = p; s1 += p;
        }
        s0 += __shfl_xor_sync(0xffffffffu, s0, 1);
        s0 += __shfl_xor_sync(0xffffffffu, s0, 2);
        s1 += __shfl_xor_sync(0xffffffffu, s1, 1);
        s1 += __shfl_xor_sync(0xffffffffu, s1, 2);
        l0 = l0 * c0 + s0;  l1 = l1 * c1 + s1;
        mp0 = mn0;          mp1 = mn1;

        // ---- P fragments in-register (C -> A identity) ----
        uint32_t ph_[4][4], pl_[4][4];
        #pragma unroll
        for (int j = 0; j < 4; j++) {
            bf16split2(Dq[2*j  ][0], Dq[2*j  ][1], ph_[j][0], pl_[j][0]);
            bf16split2(Dq[2*j  ][2], Dq[2*j  ][3], ph_[j][1], pl_[j][1]);
            bf16split2(Dq[2*j+1][0], Dq[2*j+1][1], ph_[j][2], pl_[j][2]);
            bf16split2(Dq[2*j+1][2], Dq[2*j+1][3], ph_[j][3], pl_[j][3]);
        }

        // ---- O rescale + PV ----
        #pragma unroll
        for (int ns = 0; ns < 8; ns++) {
            O[ns][0] *= c0; O[ns][1] *= c0; O[ns][2] *= c1; O[ns][3] *= c1;
        }
        #pragma unroll
        for (int j = 0; j < 4; j++) {
            uint32_t vfh[4][4], vfl[4][4];
            #pragma unroll
            for (int nj = 0; nj < 4; nj++) {
                const uint32_t off =
                    SW128((uint32_t)((nj * 16 + ((lane >> 4) << 3) + (lane & 7)) * 128) + j * 32 +
                          (((uint32_t)((lane >> 3) & 1)) << 4));
                ldmx4(vfh[nj], stg + 16384 + off);
                ldmx4(vfl[nj], stg + 24576 + off);
            }
            #pragma unroll
            for (int ns = 0; ns < 8; ns++) {
                const uint32_t* fh = &vfh[ns >> 1][(ns & 1) * 2];
                const uint32_t* fl = &vfl[ns >> 1][(ns & 1) * 2];
                mma_bf16(O[ns], ph_[j], fh);
                mma_bf16(O[ns], ph_[j], fl);
                mma_bf16(O[ns], pl_[j], fh);
            }
        }
        __syncthreads();
    }

    // ---- finalize: y = O / l as bf16 hi/lo ----
    const float inv0 = 1.0f / l0, inv1 = 1.0f / l1;
    #pragma unroll
    for (int ns = 0; ns < 8; ns++) {
        const int d = ns * 8 + (lane & 3) * 2;
        const size_t idx0 = ((size_t)bb * T_ + r0g) * C_ + hh * D_ + d;
        uint32_t hw, lw;
        bf16split2(O[ns][0] * inv0, O[ns][1] * inv0, hw, lw);
        *(uint32_t*)(yh + idx0) = hw;
        *(uint32_t*)(yl + idx0) = lw;
        bf16split2(O[ns][2] * inv1, O[ns][3] * inv1, hw, lw);
        *(uint32_t*)(yh + idx0 + (size_t)8 * C_) = hw;
        *(uint32_t*)(yl + idx0 + (size_t)8 * C_) = lw;
    }
}

// ---------------------------------------------------------------------------
extern "C" void kernel_launch(void* const* d_in, const int* in_sizes, int n_in,
                              void* d_out, int out_size)
{
    const float* x    = (const float*)d_in[0];
    const int*   mask = (const int*)  d_in[1];
    const float* rel  = (const float*)d_in[2];
    const float* ref  = (const float*)d_in[3];
    const float* W[6] = {(const float*)d_in[4], (const float*)d_in[6], (const float*)d_in[8],
                         (const float*)d_in[10], (const float*)d_in[12], (const float*)d_in[14]};
    const float* bias[6] = {(const float*)d_in[5], (const float*)d_in[7], (const float*)d_in[9],
                            (const float*)d_in[11], (const float*)d_in[13], (const float*)d_in[15]};
    float* out = (float*)d_out;

    __nv_bfloat16 *xh, *xl, *rh, *rl, *wh, *wl, *yh, *yl, *qh, *ql, *kh, *kl, *vth, *vtl;
    cudaGetSymbolAddress((void**)&xh, g_xh);  cudaGetSymbolAddress((void**)&xl, g_xl);
    cudaGetSymbolAddress((void**)&rh, g_rh);  cudaGetSymbolAddress((void**)&rl, g_rl);
    cudaGetSymbolAddress((void**)&wh, g_wh);  cudaGetSymbolAddress((void**)&wl, g_wl);
    cudaGetSymbolAddress((void**)&yh, g_yh);  cudaGetSymbolAddress((void**)&yl, g_yl);
    cudaGetSymbolAddress((void**)&qh, g_qh);  cudaGetSymbolAddress((void**)&ql, g_ql);
    cudaGetSymbolAddress((void**)&kh, g_kh);  cudaGetSymbolAddress((void**)&kl, g_kl);
    cudaGetSymbolAddress((void**)&vth, g_vth); cudaGetSymbolAddress((void**)&vtl, g_vtl);

    cudaFuncSetAttribute(gemm_mma, cudaFuncAttributeMaxDynamicSharedMemorySize, GSMEM);
    cudaFuncSetAttribute(attn_mma, cudaFuncAttributeMaxDynamicSharedMemorySize, ASMEM);

    const dim3 blk(256);
    const size_t WSZ = (size_t)C_ * C_;
    const dim3 gQ(C_ / 64, (B_ * T_) / 128);                         // (12, 32)
    const dim3 gKV(C_ / 64, (B_ * T_) / 128 + (B_ * TREF_) / 128);   // (12, 40)

    // 1: x + ref splits (fused)
    splitXR<<<NX4 / 256 + NR4 / 256, blk>>>(x, ref, xh, xl, rh, rl);
    // 2: all 6 weight splits
    split6_kernel<<<dim3(C_ * C_ / 4 / 256, 6), blk>>>(W[0], W[1], W[2], W[3], W[4], W[5], wh, wl);
    // 3: Q projection -> qh/ql, pre-scaled by 0.125*log2(e)
    gemm_mma<<<gQ, blk, GSMEM>>>(xh, xl, wh + 0*WSZ, wl + 0*WSZ, bias[0],
                                 xh, xl, wh + 0*WSZ, wl + 0*WSZ, bias[0],
                                 32, T_, 0, T_, 0, T_, 2, QSC, nullptr, qh, ql);
    // 4: K + RK projections (segmented) -> kh/kl
    gemm_mma<<<gKV, blk, GSMEM>>>(xh, xl, wh + 1*WSZ, wl + 1*WSZ, bias[1],
                                  rh, rl, wh + 3*WSZ, wl + 3*WSZ, bias[3],
                                  32, T_, 0, TREF_, T_, SK_, 2, 1.f, nullptr, kh, kl);
    // 5: V + RV projections (segmented), transpose-split -> vth/vtl
    gemm_mma<<<gKV, blk, GSMEM>>>(xh, xl, wh + 2*WSZ, wl + 2*WSZ, bias[2],
                                  rh, rl, wh + 4*WSZ, wl + 4*WSZ, bias[4],
                                  32, T_, 0, TREF_, T_, SK_, 3, 1.f, nullptr, vth, vtl);
    // 6: attention (PROFILED) -> yh/yl
    attn_mma<<<dim3(T_ / 128, H_, B_), blk, ASMEM>>>(mask, rel, qh, ql, kh, kl, vth, vtl, yh, yl);
    // 7: output projection -> out
    gemm_mma<<<gQ, blk, GSMEM>>>(yh, yl, wh + 5*WSZ, wl + 5*WSZ, bias[5],
                                 yh, yl, wh + 5*WSZ, wl + 5*WSZ, bias[5],
                                 32, T_, 0, T_, 0, 0, 0, 1.f, out, nullptr, nullptr);
}

// round 15
// speedup vs baseline: 3.2834x; 1.3114x over previous
#include <cuda_runtime.h>
#include <cuda_bf16.h>
#include <cstdint>
#include <math.h>

#define B_    2
#define T_    2048
#define TREF_ 512
#define C_    768
#define H_    12
#define D_    64
#define SK_   (T_ + TREF_)
#define L2E   1.4426950408889634f
#define QSC   (0.125f * L2E)

__device__ __nv_bfloat16 g_xh[(size_t)B_ * T_ * C_],    g_xl[(size_t)B_ * T_ * C_];
__device__ __nv_bfloat16 g_rh[(size_t)B_ * TREF_ * C_], g_rl[(size_t)B_ * TREF_ * C_];
__device__ __nv_bfloat16 g_wh[6 * C_ * C_],             g_wl[6 * C_ * C_];
__device__ __nv_bfloat16 g_yh[(size_t)B_ * T_ * C_],    g_yl[(size_t)B_ * T_ * C_];
__device__ __nv_bfloat16 g_qh[(size_t)B_ * H_ * T_  * D_], g_ql[(size_t)B_ * H_ * T_ * D_];
__device__ __nv_bfloat16 g_kh[(size_t)B_ * H_ * SK_ * D_], g_kl[(size_t)B_ * H_ * SK_ * D_];
__device__ __nv_bfloat16 g_vth[(size_t)B_ * H_ * D_ * SK_], g_vtl[(size_t)B_ * H_ * D_ * SK_];

// ---------------- helpers ----------------
__device__ __forceinline__ uint32_t smem_u32(const void* p) {
    uint32_t a;
    asm("{ .reg .u64 t; cvta.to.shared.u64 t, %1; cvt.u32.u64 %0, t; }" : "=r"(a) : "l"(p));
    return a;
}
#define SW128(o) ((o) ^ (((o) >> 3) & 0x70))

__device__ __forceinline__ void ldmx4(uint32_t* r, uint32_t addr) {
    asm volatile("ldmatrix.sync.aligned.m8n8.x4.shared.b16 {%0,%1,%2,%3}, [%4];"
                 : "=r"(r[0]), "=r"(r[1]), "=r"(r[2]), "=r"(r[3]) : "r"(addr));
}
__device__ __forceinline__ void mma_bf16(float* d, const uint32_t* a, const uint32_t* b) {
    asm volatile("mma.sync.aligned.m16n8k16.row.col.f32.bf16.bf16.f32 "
                 "{%0,%1,%2,%3}, {%4,%5,%6,%7}, {%8,%9}, {%0,%1,%2,%3};"
                 : "+f"(d[0]), "+f"(d[1]), "+f"(d[2]), "+f"(d[3])
                 : "r"(a[0]), "r"(a[1]), "r"(a[2]), "r"(a[3]), "r"(b[0]), "r"(b[1]));
}
__device__ __forceinline__ void cp16(uint32_t saddr, const void* g) {
    asm volatile("cp.async.cg.shared.global [%0], [%1], 16;" :: "r"(saddr), "l"(g));
}
#define CP_COMMIT() asm volatile("cp.async.commit_group;" ::: "memory")
#define CP_WAIT(n)  asm volatile("cp.async.wait_group %0;" :: "n"(n) : "memory")

__device__ __forceinline__ float ex2(float x) {
    float r;
    asm("ex2.approx.f32 %0, %1;" : "=f"(r) : "f"(x));
    return r;
}
__device__ __forceinline__ void bf16split2(float f0, float f1, uint32_t& hw, uint32_t& lw) {
    __nv_bfloat16 h0 = __float2bfloat16(f0), h1 = __float2bfloat16(f1);
    __nv_bfloat162 hp(h0, h1);
    __nv_bfloat162 lp(__float2bfloat16(f0 - __bfloat162float(h0)),
                      __float2bfloat16(f1 - __bfloat162float(h1)));
    hw = *(uint32_t*)&hp; lw = *(uint32_t*)&lp;
}

// ---------------- fused x+ref split ----------------
#define NX4 (B_ * T_ * C_ / 4)
#define NR4 (B_ * TREF_ * C_ / 4)
__global__ __launch_bounds__(256)
void splitXR(const float* __restrict__ x, const float* __restrict__ ref,
             __nv_bfloat16* __restrict__ xh, __nv_bfloat16* __restrict__ xl,
             __nv_bfloat16* __restrict__ rh, __nv_bfloat16* __restrict__ rl)
{
    const int bx = blockIdx.x;
    const float* src; __nv_bfloat16 *hi, *lo; int i;
    if (bx < NX4 / 256) { src = x;   hi = xh; lo = xl; i = bx * 256 + threadIdx.x; }
    else                { src = ref; hi = rh; lo = rl; i = (bx - NX4 / 256) * 256 + threadIdx.x; }
    const float4 a = ((const float4*)src)[i];
    uint32_t h0, l0, h1, l1;
    bf16split2(a.x, a.y, h0, l0);
    bf16split2(a.z, a.w, h1, l1);
    ((uint32_t*)hi)[2*i+0] = h0; ((uint32_t*)hi)[2*i+1] = h1;
    ((uint32_t*)lo)[2*i+0] = l0; ((uint32_t*)lo)[2*i+1] = l1;
}

__global__ __launch_bounds__(256)
void split6_kernel(const float* w0, const float* w1, const float* w2,
                   const float* w3, const float* w4, const float* w5,
                   __nv_bfloat16* __restrict__ hi, __nv_bfloat16* __restrict__ lo)
{
    const float* ws[6] = {w0, w1, w2, w3, w4, w5};
    const int wi = blockIdx.y;
    const int i = blockIdx.x * 256 + threadIdx.x;
    const float4 a = ((const float4*)ws[wi])[i];
    const size_t o = (size_t)wi * (C_ * C_ / 2) + i * 2;
    uint32_t h0, l0, h1, l1;
    bf16split2(a.x, a.y, h0, l0);
    bf16split2(a.z, a.w, h1, l1);
    ((uint32_t*)hi)[o + 0] = h0; ((uint32_t*)hi)[o + 1] = h1;
    ((uint32_t*)lo)[o + 0] = l0; ((uint32_t*)lo)[o + 1] = l1;
}

// ---------------- split-bf16 mma.sync GEMM (unchanged) ----------------
#define STSZ  49152
#define GSMEM (2 * STSZ)

__device__ __forceinline__ void cp_stage(uint32_t sbase,
    const __nv_bfloat16* __restrict__ Ah, const __nv_bfloat16* __restrict__ Al,
    const __nv_bfloat16* __restrict__ Bh, const __nv_bfloat16* __restrict__ Bl,
    int m0, int n0, int k0, int tid)
{
    #pragma unroll
    for (int i = 0; i < 4; i++) {
        const int u = tid + 256 * i, r = u >> 3, g = u & 7;
        const size_t go = (size_t)(m0 + r) * C_ + k0 + g * 8;
        const uint32_t so = SW128((uint32_t)(r * 128 + g * 16));
        cp16(sbase + so,         Ah + go);
        cp16(sbase + 16384 + so, Al + go);
    }
    #pragma unroll
    for (int i = 0; i < 2; i++) {
        const int u = tid + 256 * i, r = u >> 3, g = u & 7;
        const size_t go = (size_t)(n0 + r) * C_ + k0 + g * 8;
        const uint32_t so = SW128((uint32_t)(r * 128 + g * 16));
        cp16(sbase + 32768 + so, Bh + go);
        cp16(sbase + 40960 + so, Bl + go);
    }
}

__device__ __forceinline__ void mma_block3(float Dv[2][4][4],
    uint32_t baseAh, uint32_t baseAl, uint32_t baseBh, uint32_t baseBl,
    int arow0, uint32_t akb, int brow0, uint32_t bkb)
{
    #pragma unroll
    for (int ks = 0; ks < 4; ks++) {
        uint32_t ah[2][4], al[2][4], bh[2][4], bl[2][4];
        #pragma unroll
        for (int ms = 0; ms < 2; ms++) {
            const uint32_t off = SW128((uint32_t)((arow0 + ms * 16) * 128) + ks * 32 + akb);
            ldmx4(ah[ms], baseAh + off);
            ldmx4(al[ms], baseAl + off);
        }
        #pragma unroll
        for (int nj = 0; nj < 2; nj++) {
            const uint32_t off = SW128((uint32_t)((brow0 + nj * 16) * 128) + ks * 32 + bkb);
            ldmx4(bh[nj], baseBh + off);
            ldmx4(bl[nj], baseBl + off);
        }
        #pragma unroll
        for (int ms = 0; ms < 2; ms++)
            #pragma unroll
            for (int ns = 0; ns < 4; ns++) {
                const uint32_t* fh = &bh[ns >> 1][(ns & 1) * 2];
                const uint32_t* fl = &bl[ns >> 1][(ns & 1) * 2];
                mma_bf16(Dv[ms][ns], ah[ms], fh);
                mma_bf16(Dv[ms][ns], ah[ms], fl);
                mma_bf16(Dv[ms][ns], al[ms], fh);
            }
    }
}

__global__ __launch_bounds__(256)
void gemm_mma(const __nv_bfloat16* Ah0, const __nv_bfloat16* Al0,
              const __nv_bfloat16* Wh0, const __nv_bfloat16* Wl0, const float* bias0,
              const __nv_bfloat16* Ah1, const __nv_bfloat16* Al1,
              const __nv_bfloat16* Wh1, const __nv_bfloat16* Wl1, const float* bias1,
              int splitY, int Trows0, int toff0, int Trows1, int toff1,
              int SKo, int mode, float oscale,
              float* out, __nv_bfloat16* oh, __nv_bfloat16* ol)
{
    extern __shared__ char smem[];
    const uint32_t sb = smem_u32(smem);
    const int tid = threadIdx.x, lane = tid & 31, wid = tid >> 5;
    const int wm = wid & 3, wn = wid >> 2;
    const int by = blockIdx.y;
    const bool segB = by >= splitY;
    const __nv_bfloat16* Ah = segB ? Ah1 : Ah0;
    const __nv_bfloat16* Al = segB ? Al1 : Al0;
    const __nv_bfloat16* Wh = segB ? Wh1 : Wh0;
    const __nv_bfloat16* Wl = segB ? Wl1 : Wl0;
    const float* bias = segB ? bias1 : bias0;
    const int Trows = segB ? Trows1 : Trows0;
    const int toff  = segB ? toff1  : toff0;
    const int n0 = blockIdx.x * 64;
    const int m0 = (segB ? (by - splitY) : by) * 128;

    float D[2][4][4] = {};
    cp_stage(sb, Ah, Al, Wh, Wl, m0, n0, 0, tid);
    CP_COMMIT();

    const int arow0 = wm * 32 + (lane & 15);
    const uint32_t akb = ((uint32_t)(lane >> 4)) << 4;
    const int brow0 = wn * 32 + ((lane >> 4) << 3) + (lane & 7);
    const uint32_t bkb = ((uint32_t)((lane >> 3) & 1)) << 4;

    #pragma unroll 1
    for (int c = 0; c < 12; c++) {
        if (c + 1 < 12) {
            cp_stage(sb + ((c + 1) & 1) * STSZ, Ah, Al, Wh, Wl, m0, n0, (c + 1) * 64, tid);
            CP_COMMIT();
            CP_WAIT(1);
        } else CP_WAIT(0);
        __syncthreads();
        const uint32_t bA = sb + (c & 1) * STSZ;
        mma_block3(D, bA, bA + 16384, bA + 32768, bA + 40960, arow0, akb, brow0, bkb);
        __syncthreads();
    }

    const int h = n0 >> 6;
    if (mode == 3) {
        float* S = (float*)smem;
        #pragma unroll
        for (int ns = 0; ns < 4; ns++) {
            const int col = wn * 32 + ns * 8 + (lane & 3) * 2;
            const float b0 = bias[n0 + col], b1 = bias[n0 + col + 1];
            #pragma unroll
            for (int ms = 0; ms < 2; ms++)
                #pragma unroll
                for (int half = 0; half < 2; half++) {
                    const int r = wm * 32 + ms * 16 + (lane >> 2) + half * 8;
                    *(float2*)&S[r * 68 + col] =
                        make_float2(D[ms][ns][half*2] + b0, D[ms][ns][half*2+1] + b1);
                }
        }
        __syncthreads();
        const int bi = m0 / Trows, t0 = m0 % Trows;
        const int bh = bi * H_ + h;
        #pragma unroll
        for (int it = 0; it < 4; it++) {
            const int u = tid + 256 * it, d = u >> 4, ch = u & 15;
            float f[8];
            #pragma unroll
            for (int p = 0; p < 8; p++) f[p] = S[(ch * 8 + p) * 68 + d];
            uint32_t hw[4], lw[4];
            #pragma unroll
            for (int p = 0; p < 4; p++) bf16split2(f[2*p], f[2*p+1], hw[p], lw[p]);
            const size_t o = ((size_t)bh * D_ + d) * SK_ + toff + t0 + ch * 8;
            *(uint4*)(oh + o) = make_uint4(hw[0], hw[1], hw[2], hw[3]);
            *(uint4*)(ol + o) = make_uint4(lw[0], lw[1], lw[2], lw[3]);
        }
    } else {
        #pragma unroll
        for (int ns = 0; ns < 4; ns++) {
            const int col = n0 + wn * 32 + ns * 8 + (lane & 3) * 2;
            const float b0 = bias[col], b1 = bias[col + 1];
            #pragma unroll
            for (int ms = 0; ms < 2; ms++) {
                const int r0 = m0 + wm * 32 + ms * 16 + (lane >> 2);
                #pragma unroll
                for (int half = 0; half < 2; half++) {
                    const int m = r0 + half * 8;
                    const float v0 = D[ms][ns][half*2+0] + b0;
                    const float v1 = D[ms][ns][half*2+1] + b1;
                    if (mode == 0) {
                        *(float2*)(out + (size_t)m * C_ + col) = make_float2(v0, v1);
                    } else {
                        const int bi = m / Trows, t = m % Trows, d = col - n0;
                        const size_t idx = ((size_t)(bi * H_ + h) * SKo + t + toff) * D_ + d;
                        uint32_t hw, lw;
                        bf16split2(v0 * oscale, v1 * oscale, hw, lw);
                        *(uint32_t*)(oh + idx) = hw;
                        *(uint32_t*)(ol + idx) = lw;
                    }
                }
            }
        }
    }
}

// ---------------- register-softmax flash attention, 64-row blocks ----------
// 8 warps: warp (wr, wk) = 16 q-rows x 32 keys (key half). Independent online
// softmax per warp over its key subset; split-KV merge across wk at the end.
#define AS_QH  0
#define AS_QL  8192
#define AS_STG 16384           /* +s*32768: KH | KL +8192 | VTH +16384 | VTL +24576 */
#define ASMEM  (16384 + 2 * 32768)

__global__ __launch_bounds__(256)
void attn_mma(const int* __restrict__ mask, const float* __restrict__ rel,
              const __nv_bfloat16* __restrict__ qh, const __nv_bfloat16* __restrict__ ql,
              const __nv_bfloat16* __restrict__ kh, const __nv_bfloat16* __restrict__ kl,
              const __nv_bfloat16* __restrict__ vth, const __nv_bfloat16* __restrict__ vtl,
              __nv_bfloat16* __restrict__ yh, __nv_bfloat16* __restrict__ yl)
{
    extern __shared__ char smem[];
    const uint32_t sb = smem_u32(smem);
    const float NI = __int_as_float(0xff800000);

    const int tid = threadIdx.x, lane = tid & 31, wid = tid >> 5;
    const int wr = wid & 3, wk = wid >> 2;          // row group / key half
    const int qb = blockIdx.x, hh = blockIdx.y, bb = blockIdx.z;
    const int tq0 = qb * 64, bh = bb * H_ + hh;
    const int rl0 = wr * 16 + (lane >> 2);          // local row (and +8)
    const int r0g = tq0 + rl0;

    // initial loads: Q (persist) + stage 0
    {
        const size_t qbase = ((size_t)bh * T_ + tq0) * D_;
        #pragma unroll
        for (int it = 0; it < 2; it++) {
            const int u = tid + 256 * it, r = u >> 3, g = u & 7;
            const uint32_t so = SW128((uint32_t)(r * 128 + g * 16));
            cp16(sb + AS_QH + so, qh + qbase + (size_t)r * D_ + g * 8);
            cp16(sb + AS_QL + so, ql + qbase + (size_t)r * D_ + g * 8);
        }
        const size_t kbase = (size_t)bh * SK_ * D_;
        const size_t vbase = (size_t)bh * D_ * SK_;
        #pragma unroll
        for (int it = 0; it < 2; it++) {
            const int u = tid + 256 * it, r = u >> 3, g = u & 7;
            const uint32_t so = SW128((uint32_t)(r * 128 + g * 16));
            cp16(sb + AS_STG + so,         kh + kbase + (size_t)r * D_ + g * 8);
            cp16(sb + AS_STG + 8192 + so,  kl + kbase + (size_t)r * D_ + g * 8);
            cp16(sb + AS_STG + 16384 + so, vth + vbase + (size_t)r * SK_ + g * 8);
            cp16(sb + AS_STG + 24576 + so, vtl + vbase + (size_t)r * SK_ + g * 8);
        }
        CP_COMMIT();
    }

    float O[8][4] = {};
    float mp0 = NI, mp1 = NI, l0 = 0.f, l1 = 0.f;

    #pragma unroll 1
    for (int kb = 0; kb < SK_ / 64; kb++) {
        if (kb + 1 < SK_ / 64) {
            const uint32_t st = sb + AS_STG + ((kb + 1) & 1) * 32768;
            const size_t kbase = ((size_t)bh * SK_ + (kb + 1) * 64) * D_;
            const size_t vbase = (size_t)bh * D_ * SK_ + (kb + 1) * 64;
            #pragma unroll
            for (int it = 0; it < 2; it++) {
                const int u = tid + 256 * it, r = u >> 3, g = u & 7;
                const uint32_t so = SW128((uint32_t)(r * 128 + g * 16));
                cp16(st + so,         kh + kbase + (size_t)r * D_ + g * 8);
                cp16(st + 8192 + so,  kl + kbase + (size_t)r * D_ + g * 8);
                cp16(st + 16384 + so, vth + vbase + (size_t)r * SK_ + g * 8);
                cp16(st + 24576 + so, vtl + vbase + (size_t)r * SK_ + g * 8);
            }
            CP_COMMIT();
            CP_WAIT(1);
        } else CP_WAIT(0);
        __syncthreads();

        const uint32_t stg = sb + AS_STG + (kb & 1) * 32768;

        // ---- QK over this warp's 32 keys: Dq[4 n-tiles][4] ----
        float Dq[4][4] = {};
        #pragma unroll
        for (int ks = 0; ks < 4; ks++) {
            uint32_t qfh[4], qfl[4];
            const uint32_t qoff =
                SW128((uint32_t)((wr * 16 + (lane & 15)) * 128) + ks * 32 + (((uint32_t)(lane >> 4)) << 4));
            ldmx4(qfh, sb + AS_QH + qoff);
            ldmx4(qfl, sb + AS_QL + qoff);
            uint32_t kfh[2][4], kfl[2][4];
            #pragma unroll
            for (int nj = 0; nj < 2; nj++) {
                const uint32_t off =
                    SW128((uint32_t)((wk * 32 + nj * 16 + ((lane >> 4) << 3) + (lane & 7)) * 128) +
                          ks * 32 + (((uint32_t)((lane >> 3) & 1)) << 4));
                ldmx4(kfh[nj], stg + off);
                ldmx4(kfl[nj], stg + 8192 + off);
            }
            #pragma unroll
            for (int ns = 0; ns < 4; ns++) {
                const uint32_t* fh = &kfh[ns >> 1][(ns & 1) * 2];
                const uint32_t* fl = &kfl[ns >> 1][(ns & 1) * 2];
                mma_bf16(Dq[ns], qfh, fh);
                mma_bf16(Dq[ns], qfh, fl);
                mma_bf16(Dq[ns], qfl, fh);
            }
        }

        // ---- bias (mask/rel) in-register ----
        if (kb < T_ / 64) {
            const int colb = kb * 64 + wk * 32 + (lane & 3) * 2;
            const size_t mrow0 = ((size_t)bb * T_ + r0g) * T_ + colb;
            const size_t rrow0 = ((size_t)hh * T_ + r0g) * T_ + colb;
            #pragma unroll
            for (int ns = 0; ns < 4; ns++) {
                const int o = ns * 8;
                const int2   mv0 = *(const int2*)  (mask + mrow0 + o);
                const float2 rv0 = *(const float2*)(rel  + rrow0 + o);
                Dq[ns][0] = mv0.x ? NI : fmaf(rv0.x, L2E, Dq[ns][0]);
                Dq[ns][1] = mv0.y ? NI : fmaf(rv0.y, L2E, Dq[ns][1]);
                const int2   mv1 = *(const int2*)  (mask + mrow0 + (size_t)8 * T_ + o);
                const float2 rv1 = *(const float2*)(rel  + rrow0 + (size_t)8 * T_ + o);
                Dq[ns][2] = mv1.x ? NI : fmaf(rv1.x, L2E, Dq[ns][2]);
                Dq[ns][3] = mv1.y ? NI : fmaf(rv1.y, L2E, Dq[ns][3]);
            }
        }

        // ---- per-warp online softmax (quad-lane reductions) ----
        float m0l = NI, m1l = NI;
        #pragma unroll
        for (int ns = 0; ns < 4; ns++) {
            m0l = fmaxf(m0l, fmaxf(Dq[ns][0], Dq[ns][1]));
            m1l = fmaxf(m1l, fmaxf(Dq[ns][2], Dq[ns][3]));
        }
        m0l = fmaxf(m0l, __shfl_xor_sync(0xffffffffu, m0l, 1));
        m0l = fmaxf(m0l, __shfl_xor_sync(0xffffffffu, m0l, 2));
        m1l = fmaxf(m1l, __shfl_xor_sync(0xffffffffu, m1l, 1));
        m1l = fmaxf(m1l, __shfl_xor_sync(0xffffffffu, m1l, 2));
        const float mn0 = fmaxf(mp0, m0l), mn1 = fmaxf(mp1, m1l);
        const float c0 = (mp0 == NI) ? 0.f : ex2(mp0 - mn0);
        const float c1 = (mp1 == NI) ? 0.f : ex2(mp1 - mn1);
        float s0 = 0.f, s1 = 0.f;
        #pragma unroll
        for (int ns = 0; ns < 4; ns++) {
            float p;
            p = (Dq[ns][0] == NI || mn0 == NI) ? 0.f : ex2(Dq[ns][0] - mn0); Dq[ns][0] = p; s0 += p;
            p = (Dq[ns][1] == NI || mn0 == NI) ? 0.f : ex2(Dq[ns][1] - mn0); Dq[ns][1] = p; s0 += p;
            p = (Dq[ns][2] == NI || mn1 == NI) ? 0.f : ex2(Dq[ns][2] - mn1); Dq[ns][2] = p; s1 += p;
            p = (Dq[ns][3] == NI || mn1 == NI) ? 0.f : ex2(Dq[ns][3] - mn1); Dq[ns][3] = p; s1 += p;
        }
        s0 += __shfl_xor_sync(0xffffffffu, s0, 1);
        s0 += __shfl_xor_sync(0xffffffffu, s0, 2);
        s1 += __shfl_xor_sync(0xffffffffu, s1, 1);
        s1 += __shfl_xor_sync(0xffffffffu, s1, 2);
        l0 = l0 * c0 + s0;  l1 = l1 * c1 + s1;
        mp0 = mn0;          mp1 = mn1;

        // ---- P fragments (C->A identity), 2 k16 groups over 32 keys ----
        uint32_t ph_[2][4], pl_[2][4];
        #pragma unroll
        for (int j = 0; j < 2; j++) {
            bf16split2(Dq[2*j  ][0], Dq[2*j  ][1], ph_[j][0], pl_[j][0]);
            bf16split2(Dq[2*j  ][2], Dq[2*j  ][3], ph_[j][1], pl_[j][1]);
            bf16split2(Dq[2*j+1][0], Dq[2*j+1][1], ph_[j][2], pl_[j][2]);
            bf16split2(Dq[2*j+1][2], Dq[2*j+1][3], ph_[j][3], pl_[j][3]);
        }

        // ---- O rescale + PV (V k-dim = this warp's 32 keys) ----
        #pragma unroll
        for (int ns = 0; ns < 8; ns++) {
            O[ns][0] *= c0; O[ns][1] *= c0; O[ns][2] *= c1; O[ns][3] *= c1;
        }
        #pragma unroll
        for (int j = 0; j < 2; j++) {
            uint32_t vfh[4][4], vfl[4][4];
            #pragma unroll
            for (int nj = 0; nj < 4; nj++) {
                const uint32_t off =
                    SW128((uint32_t)((nj * 16 + ((lane >> 4) << 3) + (lane & 7)) * 128) +
                          (wk * 2 + j) * 32 + (((uint32_t)((lane >> 3) & 1)) << 4));
                ldmx4(vfh[nj], stg + 16384 + off);
                ldmx4(vfl[nj], stg + 24576 + off);
            }
            #pragma unroll
            for (int ns = 0; ns < 8; ns++) {
                const uint32_t* fh = &vfh[ns >> 1][(ns & 1) * 2];
                const uint32_t* fl = &vfl[ns >> 1][(ns & 1) * 2];
                mma_bf16(O[ns], ph_[j], fh);
                mma_bf16(O[ns], ph_[j], fl);
                mma_bf16(O[ns], pl_[j], fh);
            }
        }
        __syncthreads();
    }

    // ---- split-KV merge across wk halves via smem ----
    float* Osh = (float*)(smem + AS_STG);            // 64 x 68 fp32
    float* msh = (float*)(smem + AS_STG + 64 * 68 * 4);
    float* lsh = msh + 64;
    __syncthreads();
    if (wk == 1) {
        #pragma unroll
        for (int ns = 0; ns < 8; ns++) {
            const int d = ns * 8 + (lane & 3) * 2;
            *(float2*)&Osh[rl0 * 68 + d]       = make_float2(O[ns][0], O[ns][1]);
            *(float2*)&Osh[(rl0 + 8) * 68 + d] = make_float2(O[ns][2], O[ns][3]);
        }
        if ((lane & 3) == 0) {
            msh[rl0] = mp0; lsh[rl0] = l0;
            msh[rl0 + 8] = mp1; lsh[rl0 + 8] = l1;
        }
    }
    __syncthreads();
    if (wk == 0) {
        const float mB0 = msh[rl0],     lB0 = lsh[rl0];
        const float mB1 = msh[rl0 + 8], lB1 = lsh[rl0 + 8];
        const float mm0 = fmaxf(mp0, mB0), mm1 = fmaxf(mp1, mB1);
        const float cA0 = ex2(mp0 - mm0), cB0 = ex2(mB0 - mm0);
        const float cA1 = ex2(mp1 - mm1), cB1 = ex2(mB1 - mm1);
        const float inv0 = 1.0f / (l0 * cA0 + lB0 * cB0);
        const float inv1 = 1.0f / (l1 * cA1 + lB1 * cB1);
        #pragma unroll
        for (int ns = 0; ns < 8; ns++) {
            const int d = ns * 8 + (lane & 3) * 2;
            const float2 b0 = *(const float2*)&Osh[rl0 * 68 + d];
            const float2 b1 = *(const float2*)&Osh[(rl0 + 8) * 68 + d];
            const size_t idx0 = ((size_t)bb * T_ + r0g) * C_ + hh * D_ + d;
            uint32_t hw, lw;
            bf16split2((O[ns][0] * cA0 + b0.x * cB0) * inv0,
                       (O[ns][1] * cA0 + b0.y * cB0) * inv0, hw, lw);
            *(uint32_t*)(yh + idx0) = hw;
            *(uint32_t*)(yl + idx0) = lw;
            bf16split2((O[ns][2] * cA1 + b1.x * cB1) * inv1,
                       (O[ns][3] * cA1 + b1.y * cB1) * inv1, hw, lw);
            *(uint32_t*)(yh + idx0 + (size_t)8 * C_) = hw;
            *(uint32_t*)(yl + idx0 + (size_t)8 * C_) = lw;
        }
    }
}

// ---------------------------------------------------------------------------
extern "C" void kernel_launch(void* const* d_in, const int* in_sizes, int n_in,
                              void* d_out, int out_size)
{
    const float* x    = (const float*)d_in[0];
    const int*   mask = (const int*)  d_in[1];
    const float* rel  = (const float*)d_in[2];
    const float* ref  = (const float*)d_in[3];
    const float* W[6] = {(const float*)d_in[4], (const float*)d_in[6], (const float*)d_in[8],
                         (const float*)d_in[10], (const float*)d_in[12], (const float*)d_in[14]};
    const float* bias[6] = {(const float*)d_in[5], (const float*)d_in[7], (const float*)d_in[9],
                            (const float*)d_in[11], (const float*)d_in[13], (const float*)d_in[15]};
    float* out = (float*)d_out;

    __nv_bfloat16 *xh, *xl, *rh, *rl, *wh, *wl, *yh, *yl, *qh, *ql, *kh, *kl, *vth, *vtl;
    cudaGetSymbolAddress((void**)&xh, g_xh);  cudaGetSymbolAddress((void**)&xl, g_xl);
    cudaGetSymbolAddress((void**)&rh, g_rh);  cudaGetSymbolAddress((void**)&rl, g_rl);
    cudaGetSymbolAddress((void**)&wh, g_wh);  cudaGetSymbolAddress((void**)&wl, g_wl);
    cudaGetSymbolAddress((void**)&yh, g_yh);  cudaGetSymbolAddress((void**)&yl, g_yl);
    cudaGetSymbolAddress((void**)&qh, g_qh);  cudaGetSymbolAddress((void**)&ql, g_ql);
    cudaGetSymbolAddress((void**)&kh, g_kh);  cudaGetSymbolAddress((void**)&kl, g_kl);
    cudaGetSymbolAddress((void**)&vth, g_vth); cudaGetSymbolAddress((void**)&vtl, g_vtl);

    cudaFuncSetAttribute(gemm_mma, cudaFuncAttributeMaxDynamicSharedMemorySize, GSMEM);
    cudaFuncSetAttribute(attn_mma, cudaFuncAttributeMaxDynamicSharedMemorySize, ASMEM);

    const dim3 blk(256);
    const size_t WSZ = (size_t)C_ * C_;
    const dim3 gQ(C_ / 64, (B_ * T_) / 128);                         // (12, 32)
    const dim3 gKV(C_ / 64, (B_ * T_) / 128 + (B_ * TREF_) / 128);   // (12, 40)

    // 1: x + ref splits
    splitXR<<<NX4 / 256 + NR4 / 256, blk>>>(x, ref, xh, xl, rh, rl);
    // 2: all 6 weight splits
    split6_kernel<<<dim3(C_ * C_ / 4 / 256, 6), blk>>>(W[0], W[1], W[2], W[3], W[4], W[5], wh, wl);
    // 3: Q projection (pre-scaled by 0.125*log2(e))
    gemm_mma<<<gQ, blk, GSMEM>>>(xh, xl, wh + 0*WSZ, wl + 0*WSZ, bias[0],
                                 xh, xl, wh + 0*WSZ, wl + 0*WSZ, bias[0],
                                 32, T_, 0, T_, 0, T_, 2, QSC, nullptr, qh, ql);
    // 4: K + RK projections
    gemm_mma<<<gKV, blk, GSMEM>>>(xh, xl, wh + 1*WSZ, wl + 1*WSZ, bias[1],
                                  rh, rl, wh + 3*WSZ, wl + 3*WSZ, bias[3],
                                  32, T_, 0, TREF_, T_, SK_, 2, 1.f, nullptr, kh, kl);
    // 5: V + RV projections, transpose-split
    gemm_mma<<<gKV, blk, GSMEM>>>(xh, xl, wh + 2*WSZ, wl + 2*WSZ, bias[2],
                                  rh, rl, wh + 4*WSZ, wl + 4*WSZ, bias[4],
                                  32, T_, 0, TREF_, T_, SK_, 3, 1.f, nullptr, vth, vtl);
    // 6: attention (64-row blocks, grid 768)
    attn_mma<<<dim3(T_ / 64, H_, B_), blk, ASMEM>>>(mask, rel, qh, ql, kh, kl, vth, vtl, yh, yl);
    // 7: output projection
    gemm_mma<<<gQ, blk, GSMEM>>>(yh, yl, wh + 5*WSZ, wl + 5*WSZ, bias[5],
                                 yh, yl, wh + 5*WSZ, wl + 5*WSZ, bias[5],
                                 32, T_, 0, T_, 0, 0, 0, 1.f, out, nullptr, nullptr);
}